// round 2
// baseline (speedup 1.0000x reference)
#include <cuda_runtime.h>
#include <cstdint>
#include <cstddef>

#define BB 2
#define LL 2048
#define NH 16
#define DH 64
#define DM 1024
#define NQKV 3072
#define PAIRS (BB*NH)
#define SCALE 0.125f
#define LN_EPS 1e-5f

// ---------------- scratch (static device globals; no allocation) ----------------
__device__ float g_qkv[(size_t)BB*LL*NQKV];      // [b, i, 3072]   q|k|v
__device__ float g_rk [(size_t)LL*DM];           // [r, 1024]
__device__ float g_bd [(size_t)PAIRS*LL*LL];     // [p, i, r]  537 MB
__device__ float g_ctx[(size_t)BB*LL*DM];        // [b, i, 1024]
__device__ float g_att[(size_t)BB*LL*DM];        // [b, i, 1024]
__device__ int   g_mask_mode;                    // 0=uint8, 1=int32, 2=float32
__device__ unsigned char g_mask[BB*LL];          // normalized key mask

// ---------------- mask dtype sniffing + normalization ---------------------------
// The harness may deliver the bool attn_mask as uint8, int32 or float32. The
// first 4096 bytes are in-bounds for all three. Signatures:
//   float32 0.0/1.0 : bytes 00 00 00 00 / 00 00 80 3f  -> some byte > 1
//   int32   0/1     : bytes at pos%4 != 0 are all zero, bytes in {0,1}
//   uint8   0/1     : random 0/1 bytes at every position
__global__ void mask_detect(const unsigned char* __restrict__ m) {
    __shared__ int flag_off4;   // nonzero byte at pos%4 != 0
    __shared__ int flag_big;    // byte value > 1
    if (threadIdx.x == 0) { flag_off4 = 0; flag_big = 0; }
    __syncthreads();
    int loc_off4 = 0, loc_big = 0;
    for (int i = threadIdx.x; i < BB * LL; i += blockDim.x) {
        unsigned char v = m[i];
        if (v != 0 && (i & 3) != 0) loc_off4 = 1;
        if (v > 1) loc_big = 1;
    }
    if (loc_off4) atomicOr(&flag_off4, 1);
    if (loc_big)  atomicOr(&flag_big, 1);
    __syncthreads();
    if (threadIdx.x == 0)
        g_mask_mode = flag_big ? 2 : (flag_off4 ? 0 : 1);
}

__global__ void mask_convert(const void* __restrict__ m) {
    int i = blockIdx.x * blockDim.x + threadIdx.x;
    if (i >= BB * LL) return;
    int mode = g_mask_mode;
    unsigned char r;
    if (mode == 0)      r = ((const unsigned char*)m)[i] != 0;
    else if (mode == 1) r = ((const int*)m)[i] != 0;
    else                r = ((const float*)m)[i] != 0.0f;
    g_mask[i] = r;
}

// ---------------- generic SGEMM NN: C[M,N] = A[M,K] @ B[K,N] --------------------
// BM=BN=128, BK=16, 256 threads, 8x8 microtile. M%128==0, N%128==0, K%16==0.
__global__ void __launch_bounds__(256) sgemm128(const float* __restrict__ A,
                                                const float* __restrict__ Bm,
                                                float* __restrict__ C,
                                                int M, int N, int K)
{
    __shared__ float As[16][132];   // [k][m]
    __shared__ float Bs[16][132];   // [k][n]
    const int tid = threadIdx.x;
    const int tx = tid & 15, ty = tid >> 4;
    const int m0 = blockIdx.y * 128, n0 = blockIdx.x * 128;

    float acc[8][8];
#pragma unroll
    for (int r = 0; r < 8; r++)
#pragma unroll
        for (int c = 0; c < 8; c++) acc[r][c] = 0.f;

    for (int k0 = 0; k0 < K; k0 += 16) {
#pragma unroll
        for (int s = 0; s < 2; s++) {
            int v = tid + 256 * s;            // 0..511
            int m = v >> 2;                   // 0..127
            int kq = (v & 3) * 4;             // 0,4,8,12
            float4 a = *(const float4*)(A + (size_t)(m0 + m) * K + k0 + kq);
            As[kq + 0][m] = a.x; As[kq + 1][m] = a.y;
            As[kq + 2][m] = a.z; As[kq + 3][m] = a.w;
        }
#pragma unroll
        for (int s = 0; s < 2; s++) {
            int v = tid + 256 * s;
            int k = v >> 5;                   // 0..15
            int nq = (v & 31) * 4;            // 0..124
            *(float4*)(&Bs[k][nq]) =
                *(const float4*)(Bm + (size_t)(k0 + k) * N + n0 + nq);
        }
        __syncthreads();
#pragma unroll
        for (int k = 0; k < 16; k++) {
            float a[8], b[8];
            *(float4*)(a)     = *(const float4*)(&As[k][ty * 8]);
            *(float4*)(a + 4) = *(const float4*)(&As[k][ty * 8 + 4]);
            *(float4*)(b)     = *(const float4*)(&Bs[k][tx * 8]);
            *(float4*)(b + 4) = *(const float4*)(&Bs[k][tx * 8 + 4]);
#pragma unroll
            for (int r = 0; r < 8; r++)
#pragma unroll
                for (int c = 0; c < 8; c++) acc[r][c] = fmaf(a[r], b[c], acc[r][c]);
        }
        __syncthreads();
    }
#pragma unroll
    for (int r = 0; r < 8; r++) {
        float* crow = C + (size_t)(m0 + ty * 8 + r) * N + n0 + tx * 8;
        *(float4*)(crow)     = *(float4*)(&acc[r][0]);
        *(float4*)(crow + 4) = *(float4*)(&acc[r][4]);
    }
}

// ---------------- BD GEMM-NT: BD[p,i,r] = sum_d (q[b,i,h,d]+rrb[h,d]) * rk[r,h,d]
// 128x128 tile, K=64 single-shot, 8x8 microtile, dynamic smem 67.6KB.
__global__ void __launch_bounds__(256) bd_gemm(const float* __restrict__ rrb)
{
    extern __shared__ float sm[];
    float* As = sm;               // [64][132]  [d][i]
    float* Bs = sm + 64 * 132;    // [64][132]  [d][r]

    const int p = blockIdx.z;
    const int b = p >> 4, h = p & 15;
    const int i0 = blockIdx.y * 128, r0 = blockIdx.x * 128;
    const int tid = threadIdx.x;
    const int tx = tid & 15, ty = tid >> 4;

#pragma unroll
    for (int s = 0; s < 8; s++) {
        int v = tid + 256 * s;            // 0..2047
        int m = v >> 4;                   // 0..127
        int dq = (v & 15) * 4;            // 0..60
        float4 q = *(const float4*)(g_qkv + (size_t)(b * LL + i0 + m) * NQKV + h * 64 + dq);
        float4 bi = *(const float4*)(rrb + h * 64 + dq);
        As[(dq + 0) * 132 + m] = q.x + bi.x;
        As[(dq + 1) * 132 + m] = q.y + bi.y;
        As[(dq + 2) * 132 + m] = q.z + bi.z;
        As[(dq + 3) * 132 + m] = q.w + bi.w;
        float4 rk = *(const float4*)(g_rk + (size_t)(r0 + m) * DM + h * 64 + dq);
        Bs[(dq + 0) * 132 + m] = rk.x;
        Bs[(dq + 1) * 132 + m] = rk.y;
        Bs[(dq + 2) * 132 + m] = rk.z;
        Bs[(dq + 3) * 132 + m] = rk.w;
    }
    __syncthreads();

    float acc[8][8];
#pragma unroll
    for (int r = 0; r < 8; r++)
#pragma unroll
        for (int c = 0; c < 8; c++) acc[r][c] = 0.f;

#pragma unroll 8
    for (int k = 0; k < 64; k++) {
        float a[8], bb[8];
        *(float4*)(a)      = *(const float4*)(&As[k * 132 + ty * 8]);
        *(float4*)(a + 4)  = *(const float4*)(&As[k * 132 + ty * 8 + 4]);
        *(float4*)(bb)     = *(const float4*)(&Bs[k * 132 + tx * 8]);
        *(float4*)(bb + 4) = *(const float4*)(&Bs[k * 132 + tx * 8 + 4]);
#pragma unroll
        for (int r = 0; r < 8; r++)
#pragma unroll
            for (int c = 0; c < 8; c++) acc[r][c] = fmaf(a[r], bb[c], acc[r][c]);
    }

#pragma unroll
    for (int r = 0; r < 8; r++) {
        float* crow = g_bd + ((size_t)p * LL + i0 + ty * 8 + r) * LL + r0 + tx * 8;
        *(float4*)(crow)     = *(float4*)(&acc[r][0]);
        *(float4*)(crow + 4) = *(float4*)(&acc[r][4]);
    }
}

// ---------------- fused flash attention per (b, h, 64-row tile) -----------------
__global__ void __launch_bounds__(256) attn_kernel(const float* __restrict__ rwb)
{
    extern __shared__ float sm[];
    float* Qs = sm;                 // [d][i]  64x68
    float* Ks = Qs + 64 * 68;       // [d][j]
    float* Vs = Ks + 64 * 68;       // [j][d]
    float* Ps = Vs + 64 * 68;       // [j][i]
    float* mrow = Ps + 64 * 68;     // [64]
    float* lrow = mrow + 64;        // [64]

    const int it = blockIdx.x, h = blockIdx.y, b = blockIdx.z;
    const int i0 = it * 64;
    const int p = b * NH + h;
    const int tid = threadIdx.x;
    const int tx = tid & 15, ty = tid >> 4;

    // load Q (+ r_w_bias), transposed [d][i]
#pragma unroll
    for (int s = 0; s < 4; s++) {
        int v = tid + 256 * s;            // 0..1023
        int i = v >> 4;
        int dq = (v & 15) * 4;
        float4 q = *(const float4*)(g_qkv + (size_t)(b * LL + i0 + i) * NQKV + h * 64 + dq);
        float4 bi = *(const float4*)(rwb + h * 64 + dq);
        Qs[(dq + 0) * 68 + i] = q.x + bi.x;
        Qs[(dq + 1) * 68 + i] = q.y + bi.y;
        Qs[(dq + 2) * 68 + i] = q.z + bi.z;
        Qs[(dq + 3) * 68 + i] = q.w + bi.w;
    }
    if (tid < 64) { mrow[tid] = -1e30f; lrow[tid] = 0.f; }

    float ctx[4][4];
#pragma unroll
    for (int r = 0; r < 4; r++)
#pragma unroll
        for (int c = 0; c < 4; c++) ctx[r][c] = 0.f;

    for (int jt = 0; jt < LL / 64; jt++) {
        const int j0 = jt * 64;
        __syncthreads();    // previous PV done before overwriting K/V/P
#pragma unroll
        for (int s = 0; s < 4; s++) {
            int v = tid + 256 * s;
            int j = v >> 4;
            int dq = (v & 15) * 4;
            const float* base = g_qkv + (size_t)(b * LL + j0 + j) * NQKV + h * 64 + dq;
            float4 kk = *(const float4*)(base + DM);
            Ks[(dq + 0) * 68 + j] = kk.x;
            Ks[(dq + 1) * 68 + j] = kk.y;
            Ks[(dq + 2) * 68 + j] = kk.z;
            Ks[(dq + 3) * 68 + j] = kk.w;
            *(float4*)(&Vs[j * 68 + dq]) = *(const float4*)(base + 2 * DM);
        }
        __syncthreads();

        // S = Qrw . K^T
        float sacc[4][4];
#pragma unroll
        for (int r = 0; r < 4; r++)
#pragma unroll
            for (int c = 0; c < 4; c++) sacc[r][c] = 0.f;
#pragma unroll 8
        for (int d = 0; d < 64; d++) {
            float4 a = *(const float4*)(&Qs[d * 68 + ty * 4]);
            float4 bq = *(const float4*)(&Ks[d * 68 + tx * 4]);
            float av[4] = {a.x, a.y, a.z, a.w};
            float bv[4] = {bq.x, bq.y, bq.z, bq.w};
#pragma unroll
            for (int r = 0; r < 4; r++)
#pragma unroll
                for (int c = 0; c < 4; c++) sacc[r][c] = fmaf(av[r], bv[c], sacc[r][c]);
        }

        // + shifted BD, scale, mask, online softmax
#pragma unroll
        for (int r = 0; r < 4; r++) {
            const int i = ty * 4 + r;
            const int ig = i0 + i;
            const size_t bd_row  = ((size_t)p * LL + ig) * LL;
            const size_t bd_row1 = ((size_t)p * LL + ig + 1) * LL;
            float sv[4];
#pragma unroll
            for (int c = 0; c < 4; c++) {
                int jg = j0 + tx * 4 + c;
                float bd;
                if (jg <= ig)           bd = g_bd[bd_row + (jg - ig + LL - 1)];
                else if (jg == ig + 1)  bd = 0.f;
                else                    bd = g_bd[bd_row1 + (jg - ig - 2)];
                float sc = (sacc[r][c] + bd) * SCALE;
                if (g_mask[b * LL + jg]) sc = -1e30f;
                sv[c] = sc;
            }
            float rmax = fmaxf(fmaxf(sv[0], sv[1]), fmaxf(sv[2], sv[3]));
#pragma unroll
            for (int off = 8; off >= 1; off >>= 1)
                rmax = fmaxf(rmax, __shfl_xor_sync(0xffffffffu, rmax, off));
            float mold = mrow[i];
            float mnew = fmaxf(mold, rmax);
            float psum = 0.f, pv[4];
#pragma unroll
            for (int c = 0; c < 4; c++) { pv[c] = __expf(sv[c] - mnew); psum += pv[c]; }
#pragma unroll
            for (int off = 8; off >= 1; off >>= 1)
                psum += __shfl_xor_sync(0xffffffffu, psum, off);
            float fac = __expf(mold - mnew);
#pragma unroll
            for (int c = 0; c < 4; c++) ctx[r][c] *= fac;
            if (tx == 0) { mrow[i] = mnew; lrow[i] = lrow[i] * fac + psum; }
#pragma unroll
            for (int c = 0; c < 4; c++) Ps[(tx * 4 + c) * 68 + i] = pv[c];
        }
        __syncthreads();

        // ctx += P @ V
#pragma unroll 8
        for (int k = 0; k < 64; k++) {
            float4 a = *(const float4*)(&Ps[k * 68 + ty * 4]);
            float4 bq = *(const float4*)(&Vs[k * 68 + tx * 4]);
            float av[4] = {a.x, a.y, a.z, a.w};
            float bv[4] = {bq.x, bq.y, bq.z, bq.w};
#pragma unroll
            for (int r = 0; r < 4; r++)
#pragma unroll
                for (int c = 0; c < 4; c++) ctx[r][c] = fmaf(av[r], bv[c], ctx[r][c]);
        }
    }
    __syncthreads();
#pragma unroll
    for (int r = 0; r < 4; r++) {
        int i = ty * 4 + r;
        float inv = 1.0f / lrow[i];
#pragma unroll
        for (int c = 0; c < 4; c++)
            g_ctx[(size_t)(b * LL + i0 + i) * DM + h * 64 + tx * 4 + c] = ctx[r][c] * inv;
    }
}

// ---------------- residual + LayerNorm -----------------------------------------
__global__ void __launch_bounds__(256) ln_kernel(const float* __restrict__ x,
                                                 const float* __restrict__ gamma,
                                                 const float* __restrict__ beta,
                                                 float* __restrict__ out)
{
    const int row = blockIdx.x;
    const int tid = threadIdx.x;
    __shared__ float yb[DM];
    __shared__ float red[2][8];
    __shared__ float stats[2];

    float4 xv = ((const float4*)(x + (size_t)row * DM))[tid];
    float4 av = ((const float4*)(g_att + (size_t)row * DM))[tid];
    float4 y;
    y.x = xv.x + av.x; y.y = xv.y + av.y; y.z = xv.z + av.z; y.w = xv.w + av.w;
    *(float4*)(&yb[tid * 4]) = y;
    float s  = y.x + y.y + y.z + y.w;
    float sq = y.x * y.x + y.y * y.y + y.z * y.z + y.w * y.w;
#pragma unroll
    for (int off = 16; off >= 1; off >>= 1) {
        s  += __shfl_xor_sync(0xffffffffu, s, off);
        sq += __shfl_xor_sync(0xffffffffu, sq, off);
    }
    if ((tid & 31) == 0) { red[0][tid >> 5] = s; red[1][tid >> 5] = sq; }
    __syncthreads();
    if (tid == 0) {
        float ts = 0.f, tq = 0.f;
#pragma unroll
        for (int w = 0; w < 8; w++) { ts += red[0][w]; tq += red[1][w]; }
        float mu = ts * (1.0f / DM);
        float var = tq * (1.0f / DM) - mu * mu;
        stats[0] = mu;
        stats[1] = rsqrtf(var + LN_EPS);
    }
    __syncthreads();
    float mu = stats[0], inv = stats[1];
    float4 g = ((const float4*)gamma)[tid];
    float4 be = ((const float4*)beta)[tid];
    float4 yy = *(float4*)(&yb[tid * 4]);
    float4 o;
    o.x = (yy.x - mu) * inv * g.x + be.x;
    o.y = (yy.y - mu) * inv * g.y + be.y;
    o.z = (yy.z - mu) * inv * g.z + be.z;
    o.w = (yy.w - mu) * inv * g.w + be.w;
    ((float4*)(out + (size_t)row * DM))[tid] = o;
}

// ---------------- launch ---------------------------------------------------------
extern "C" void kernel_launch(void* const* d_in, const int* in_sizes, int n_in,
                              void* d_out, int out_size)
{
    (void)in_sizes; (void)n_in; (void)out_size;
    const float* x      = (const float*)d_in[0];
    const float* relpos = (const float*)d_in[1];
    const float* rwb    = (const float*)d_in[2];
    const float* rrb    = (const float*)d_in[3];
    const void*  maskp  = d_in[4];
    const float* Wqkv   = (const float*)d_in[5];
    const float* Wrel   = (const float*)d_in[6];
    const float* Wout   = (const float*)d_in[7];
    const float* gamma  = (const float*)d_in[8];
    const float* beta   = (const float*)d_in[9];
    float* out = (float*)d_out;

    void *qkvp, *rkp, *ctxp, *attp;
    cudaGetSymbolAddress(&qkvp, g_qkv);
    cudaGetSymbolAddress(&rkp,  g_rk);
    cudaGetSymbolAddress(&ctxp, g_ctx);
    cudaGetSymbolAddress(&attp, g_att);

    const int bd_smem   = 2 * 64 * 132 * sizeof(float);        // 67584
    const int attn_smem = (4 * 64 * 68 + 128) * sizeof(float); // 70144
    cudaFuncSetAttribute(bd_gemm,     cudaFuncAttributeMaxDynamicSharedMemorySize, bd_smem);
    cudaFuncSetAttribute(attn_kernel, cudaFuncAttributeMaxDynamicSharedMemorySize, attn_smem);

    // 0) normalize the attention mask regardless of delivered dtype
    mask_detect<<<1, 256>>>((const unsigned char*)maskp);
    mask_convert<<<(BB * LL + 255) / 256, 256>>>(maskp);

    // 1) QKV = x @ W_qkv   [4096 x 3072 x 1024]
    sgemm128<<<dim3(NQKV / 128, (BB * LL) / 128), 256>>>(x, Wqkv, (float*)qkvp, BB * LL, NQKV, DM);
    // 2) RK = relpos @ W_rel  [2048 x 1024 x 1024]
    sgemm128<<<dim3(DM / 128, LL / 128), 256>>>(relpos, Wrel, (float*)rkp, LL, DM, DM);
    // 3) BD batched NT GEMMs
    bd_gemm<<<dim3(LL / 128, LL / 128, PAIRS), 256, bd_smem>>>(rrb);
    // 4) fused flash attention
    attn_kernel<<<dim3(LL / 64, NH, BB), 256, attn_smem>>>(rwb);
    // 5) attn_out = ctx @ W_out  [4096 x 1024 x 1024]
    sgemm128<<<dim3(DM / 128, (BB * LL) / 128), 256>>>((const float*)ctxp, Wout, (float*)attp, BB * LL, DM, DM);
    // 6) residual + layernorm
    ln_kernel<<<BB * LL, 256>>>(x, gamma, beta, out);
}

// round 3
// speedup vs baseline: 1.3683x; 1.3683x over previous
#include <cuda_runtime.h>
#include <cuda_bf16.h>
#include <cstdint>
#include <cstddef>
#include <cstring>

#define BB 2
#define LL 2048
#define NH 16
#define DH 64
#define DM 1024
#define NQKV 3072
#define PAIRS (BB*NH)
#define SCALE 0.125f
#define LN_EPS 1e-5f

// ---------------- scratch ----------------
__device__ float g_qkv[(size_t)BB*LL*NQKV];
__device__ float g_rk [(size_t)LL*DM];
__device__ float g_bd [(size_t)PAIRS*LL*LL];
__device__ float g_ctx[(size_t)BB*LL*DM];
__device__ float g_att[(size_t)BB*LL*DM];
__device__ int   g_mask_mode;
__device__ unsigned char g_mask[BB*LL];

// ---------------- small helpers ----------------
__device__ __forceinline__ uint32_t sptr(const void* p) {
    return (uint32_t)__cvta_generic_to_shared(p);
}
__device__ __forceinline__ void ldsm4(uint32_t (&r)[4], uint32_t addr) {
    asm volatile("ldmatrix.sync.aligned.m8n8.x4.shared.b16 {%0,%1,%2,%3},[%4];"
        : "=r"(r[0]), "=r"(r[1]), "=r"(r[2]), "=r"(r[3]) : "r"(addr));
}
__device__ __forceinline__ void ldsm4t(uint32_t (&r)[4], uint32_t addr) {
    asm volatile("ldmatrix.sync.aligned.m8n8.x4.trans.shared.b16 {%0,%1,%2,%3},[%4];"
        : "=r"(r[0]), "=r"(r[1]), "=r"(r[2]), "=r"(r[3]) : "r"(addr));
}
__device__ __forceinline__ void mma_bf16(float* d, const uint32_t* a, uint32_t b0, uint32_t b1) {
    asm volatile("mma.sync.aligned.m16n8k16.row.col.f32.bf16.bf16.f32 "
        "{%0,%1,%2,%3},{%4,%5,%6,%7},{%8,%9},{%0,%1,%2,%3};"
        : "+f"(d[0]), "+f"(d[1]), "+f"(d[2]), "+f"(d[3])
        : "r"(a[0]), "r"(a[1]), "r"(a[2]), "r"(a[3]), "r"(b0), "r"(b1));
}
// split fp32 pair -> bf16 hi plane + bf16 lo (residual) plane, packed b32
__device__ __forceinline__ void split2(float x, float y, uint32_t& h, uint32_t& l) {
    __nv_bfloat162 hv = __floats2bfloat162_rn(x, y);
    float2 hf = __bfloat1622float2(hv);
    __nv_bfloat162 lv = __floats2bfloat162_rn(x - hf.x, y - hf.y);
    h = *reinterpret_cast<uint32_t*>(&hv);
    l = *reinterpret_cast<uint32_t*>(&lv);
}

// ---------------- mask dtype sniff + normalize (unchanged, proven) -------------
__global__ void mask_detect(const unsigned char* __restrict__ m) {
    __shared__ int flag_off4, flag_big;
    if (threadIdx.x == 0) { flag_off4 = 0; flag_big = 0; }
    __syncthreads();
    int lo = 0, lb = 0;
    for (int i = threadIdx.x; i < BB * LL; i += blockDim.x) {
        unsigned char v = m[i];
        if (v != 0 && (i & 3) != 0) lo = 1;
        if (v > 1) lb = 1;
    }
    if (lo) atomicOr(&flag_off4, 1);
    if (lb) atomicOr(&flag_big, 1);
    __syncthreads();
    if (threadIdx.x == 0) g_mask_mode = flag_big ? 2 : (flag_off4 ? 0 : 1);
}
__global__ void mask_convert(const void* __restrict__ m) {
    int i = blockIdx.x * blockDim.x + threadIdx.x;
    if (i >= BB * LL) return;
    int mode = g_mask_mode;
    unsigned char r;
    if (mode == 0)      r = ((const unsigned char*)m)[i] != 0;
    else if (mode == 1) r = ((const int*)m)[i] != 0;
    else                r = ((const float*)m)[i] != 0.0f;
    g_mask[i] = r;
}

// ================================================================================
// GEMM NN: C[M,N] = A[M,K] @ B[K,N], fp32 io, bf16 split-3 tensor cores.
// Block 128x128, BK=32, 256 threads, warps 2(m) x 4(n), warp tile 64x32.
// ================================================================================
__global__ void __launch_bounds__(256) gemm_bf163(const float* __restrict__ A,
                                                  const float* __restrict__ B,
                                                  float* __restrict__ C,
                                                  int M, int N, int K)
{
    __shared__ __align__(16) unsigned short Ah[128*40], Al[128*40];
    __shared__ __align__(16) unsigned short Bh[32*136], Bl[32*136];
    const int tid = threadIdx.x, w = tid >> 5, t = tid & 31;
    const int m0 = blockIdx.y * 128, n0 = blockIdx.x * 128;
    const int wm = (w >> 2) * 64, wn = (w & 3) * 32;
    const int g = t >> 2, tg = t & 3;

    float d[4][4][4];
#pragma unroll
    for (int i = 0; i < 4; i++)
#pragma unroll
        for (int j = 0; j < 4; j++)
#pragma unroll
            for (int q = 0; q < 4; q++) d[i][j][q] = 0.f;

    for (int k0 = 0; k0 < K; k0 += 32) {
        // ---- stage A tile 128x32 ----
#pragma unroll
        for (int s = 0; s < 2; s++) {
            int idx = tid + 256 * s;
            int row = idx >> 2, kq = (idx & 3) * 8;
            const float* ap = A + (size_t)(m0 + row) * K + k0 + kq;
            float4 f0 = *(const float4*)(ap), f1 = *(const float4*)(ap + 4);
            uint32_t h[4], l[4];
            split2(f0.x, f0.y, h[0], l[0]); split2(f0.z, f0.w, h[1], l[1]);
            split2(f1.x, f1.y, h[2], l[2]); split2(f1.z, f1.w, h[3], l[3]);
            *(uint4*)(&Ah[row * 40 + kq]) = make_uint4(h[0], h[1], h[2], h[3]);
            *(uint4*)(&Al[row * 40 + kq]) = make_uint4(l[0], l[1], l[2], l[3]);
        }
        // ---- stage B tile 32x128 ----
#pragma unroll
        for (int s = 0; s < 2; s++) {
            int idx = tid + 256 * s;
            int kr = idx >> 4, nq = (idx & 15) * 8;
            const float* bp = B + (size_t)(k0 + kr) * N + n0 + nq;
            float4 f0 = *(const float4*)(bp), f1 = *(const float4*)(bp + 4);
            uint32_t h[4], l[4];
            split2(f0.x, f0.y, h[0], l[0]); split2(f0.z, f0.w, h[1], l[1]);
            split2(f1.x, f1.y, h[2], l[2]); split2(f1.z, f1.w, h[3], l[3]);
            *(uint4*)(&Bh[kr * 136 + nq]) = make_uint4(h[0], h[1], h[2], h[3]);
            *(uint4*)(&Bl[kr * 136 + nq]) = make_uint4(l[0], l[1], l[2], l[3]);
        }
        __syncthreads();

#pragma unroll
        for (int kt = 0; kt < 2; kt++) {
            uint32_t ah[4][4], al[4][4];
#pragma unroll
            for (int mt = 0; mt < 4; mt++) {
                int off = (wm + mt * 16 + (t & 15)) * 40 + kt * 16 + (t >> 4) * 8;
                ldsm4(ah[mt], sptr(&Ah[off]));
                ldsm4(al[mt], sptr(&Al[off]));
            }
#pragma unroll
            for (int np = 0; np < 2; np++) {
                uint32_t bh[4], bl[4];
                int off = (kt * 16 + (t & 15)) * 136 + wn + np * 16 + (t >> 4) * 8;
                ldsm4t(bh, sptr(&Bh[off]));
                ldsm4t(bl, sptr(&Bl[off]));
#pragma unroll
                for (int mt = 0; mt < 4; mt++) {
                    mma_bf16(d[mt][2*np],   ah[mt], bh[0], bh[1]);
                    mma_bf16(d[mt][2*np],   al[mt], bh[0], bh[1]);
                    mma_bf16(d[mt][2*np],   ah[mt], bl[0], bl[1]);
                    mma_bf16(d[mt][2*np+1], ah[mt], bh[2], bh[3]);
                    mma_bf16(d[mt][2*np+1], al[mt], bh[2], bh[3]);
                    mma_bf16(d[mt][2*np+1], ah[mt], bl[2], bl[3]);
                }
            }
        }
        __syncthreads();
    }
    // ---- epilogue ----
#pragma unroll
    for (int mt = 0; mt < 4; mt++) {
#pragma unroll
        for (int nt = 0; nt < 4; nt++) {
            int row = m0 + wm + mt * 16 + g;
            int col = n0 + wn + nt * 8 + 2 * tg;
            *(float2*)(C + (size_t)row * N + col)       = make_float2(d[mt][nt][0], d[mt][nt][1]);
            *(float2*)(C + (size_t)(row + 8) * N + col) = make_float2(d[mt][nt][2], d[mt][nt][3]);
        }
    }
}

// ================================================================================
// BD NT GEMM: BD[p,i,r] = sum_d (q[b,i,h,d]+rrb[h,d]) * rk[r,h,d].  K=64 one shot.
// ================================================================================
__global__ void __launch_bounds__(256) bd_bf163(const float* __restrict__ rrb)
{
    extern __shared__ __align__(16) unsigned short sm2[];
    unsigned short* Ahs = sm2;
    unsigned short* Als = Ahs + 128 * 72;
    unsigned short* Bhs = Als + 128 * 72;
    unsigned short* Bls = Bhs + 128 * 72;

    const int p = blockIdx.z, b = p >> 4, h = p & 15;
    const int i0 = blockIdx.y * 128, r0 = blockIdx.x * 128;
    const int tid = threadIdx.x, w = tid >> 5, t = tid & 31;
    const int wm = (w >> 2) * 64, wn = (w & 3) * 32;
    const int g = t >> 2, tg = t & 3;

#pragma unroll
    for (int s = 0; s < 4; s++) {
        int idx = tid + 256 * s;
        int row = idx >> 3, dq = (idx & 7) * 8;
        const float* qp = g_qkv + (size_t)(b * LL + i0 + row) * NQKV + h * 64 + dq;
        float4 f0 = *(const float4*)(qp), f1 = *(const float4*)(qp + 4);
        float4 b0 = *(const float4*)(rrb + h * 64 + dq);
        float4 b1 = *(const float4*)(rrb + h * 64 + dq + 4);
        f0.x += b0.x; f0.y += b0.y; f0.z += b0.z; f0.w += b0.w;
        f1.x += b1.x; f1.y += b1.y; f1.z += b1.z; f1.w += b1.w;
        uint32_t hh[4], ll[4];
        split2(f0.x, f0.y, hh[0], ll[0]); split2(f0.z, f0.w, hh[1], ll[1]);
        split2(f1.x, f1.y, hh[2], ll[2]); split2(f1.z, f1.w, hh[3], ll[3]);
        *(uint4*)(&Ahs[row * 72 + dq]) = make_uint4(hh[0], hh[1], hh[2], hh[3]);
        *(uint4*)(&Als[row * 72 + dq]) = make_uint4(ll[0], ll[1], ll[2], ll[3]);
        const float* rp = g_rk + (size_t)(r0 + row) * DM + h * 64 + dq;
        float4 r4 = *(const float4*)(rp), r5 = *(const float4*)(rp + 4);
        split2(r4.x, r4.y, hh[0], ll[0]); split2(r4.z, r4.w, hh[1], ll[1]);
        split2(r5.x, r5.y, hh[2], ll[2]); split2(r5.z, r5.w, hh[3], ll[3]);
        *(uint4*)(&Bhs[row * 72 + dq]) = make_uint4(hh[0], hh[1], hh[2], hh[3]);
        *(uint4*)(&Bls[row * 72 + dq]) = make_uint4(ll[0], ll[1], ll[2], ll[3]);
    }
    __syncthreads();

    float d[4][4][4];
#pragma unroll
    for (int i = 0; i < 4; i++)
#pragma unroll
        for (int j = 0; j < 4; j++)
#pragma unroll
            for (int q = 0; q < 4; q++) d[i][j][q] = 0.f;

#pragma unroll
    for (int kt = 0; kt < 4; kt++) {
        uint32_t ah[4][4], al[4][4];
#pragma unroll
        for (int mt = 0; mt < 4; mt++) {
            int off = (wm + mt * 16 + (t & 15)) * 72 + kt * 16 + (t >> 4) * 8;
            ldsm4(ah[mt], sptr(&Ahs[off]));
            ldsm4(al[mt], sptr(&Als[off]));
        }
#pragma unroll
        for (int np = 0; np < 2; np++) {
            uint32_t bh[4], bl[4];
            int nrow = wn + np * 16 + ((t >> 4) << 3) + (t & 7);
            int kcol = kt * 16 + ((t >> 3) & 1) * 8;
            ldsm4(bh, sptr(&Bhs[nrow * 72 + kcol]));
            ldsm4(bl, sptr(&Bls[nrow * 72 + kcol]));
#pragma unroll
            for (int mt = 0; mt < 4; mt++) {
                mma_bf16(d[mt][2*np],   ah[mt], bh[0], bh[1]);
                mma_bf16(d[mt][2*np],   al[mt], bh[0], bh[1]);
                mma_bf16(d[mt][2*np],   ah[mt], bl[0], bl[1]);
                mma_bf16(d[mt][2*np+1], ah[mt], bh[2], bh[3]);
                mma_bf16(d[mt][2*np+1], al[mt], bh[2], bh[3]);
                mma_bf16(d[mt][2*np+1], ah[mt], bl[2], bl[3]);
            }
        }
    }
#pragma unroll
    for (int mt = 0; mt < 4; mt++) {
#pragma unroll
        for (int nt = 0; nt < 4; nt++) {
            int row = i0 + wm + mt * 16 + g;
            int col = r0 + wn + nt * 8 + 2 * tg;
            float* c0 = g_bd + ((size_t)p * LL + row) * LL + col;
            float* c1 = g_bd + ((size_t)p * LL + row + 8) * LL + col;
            *(float2*)c0 = make_float2(d[mt][nt][0], d[mt][nt][1]);
            *(float2*)c1 = make_float2(d[mt][nt][2], d[mt][nt][3]);
        }
    }
}

// ================================================================================
// Flash attention, tensor cores.  Block = 128 q-rows x (b,h); 8 warps, warp = 16 rows.
// j-tiles of 64.  Q frags persist in regs; P converts S-frags -> A-frags in regs.
// ================================================================================
__global__ void __launch_bounds__(256) attn_bf163(const float* __restrict__ rwb)
{
    __shared__ __align__(16) unsigned short Ksh[64*72], Ksl[64*72];
    __shared__ __align__(16) unsigned short Vsh[64*72], Vsl[64*72];
    __shared__ float mb[64];

    const int it = blockIdx.x, h = blockIdx.y, b = blockIdx.z;
    const int i0 = it * 128;
    const int p = b * NH + h;
    const int tid = threadIdx.x, w = tid >> 5, t = tid & 31;
    const int g = t >> 2, tg = t & 3;

    // ---- Q prologue: stage rows in halves through Ks, grab frags to regs ----
    uint32_t qh[4][4], ql[4][4];
#pragma unroll
    for (int half = 0; half < 2; half++) {
        __syncthreads();
#pragma unroll
        for (int s = 0; s < 1; s++) { /* 64 rows x 64 d = 4096 floats; 16/thread */ }
#pragma unroll
        for (int s = 0; s < 2; s++) {
            int idx = tid + 256 * s;           // 0..511
            int row = idx >> 3, dq = (idx & 7) * 8;
            const float* qp = g_qkv + (size_t)(b * LL + i0 + half * 64 + row) * NQKV + h * 64 + dq;
            float4 f0 = *(const float4*)(qp), f1 = *(const float4*)(qp + 4);
            float4 b0 = *(const float4*)(rwb + h * 64 + dq);
            float4 b1 = *(const float4*)(rwb + h * 64 + dq + 4);
            f0.x += b0.x; f0.y += b0.y; f0.z += b0.z; f0.w += b0.w;
            f1.x += b1.x; f1.y += b1.y; f1.z += b1.z; f1.w += b1.w;
            uint32_t hh[4], ll[4];
            split2(f0.x, f0.y, hh[0], ll[0]); split2(f0.z, f0.w, hh[1], ll[1]);
            split2(f1.x, f1.y, hh[2], ll[2]); split2(f1.z, f1.w, hh[3], ll[3]);
            *(uint4*)(&Ksh[row * 72 + dq]) = make_uint4(hh[0], hh[1], hh[2], hh[3]);
            *(uint4*)(&Ksl[row * 72 + dq]) = make_uint4(ll[0], ll[1], ll[2], ll[3]);
        }
        __syncthreads();
        if ((w >> 2) == half) {
            int mbase = (w & 3) * 16;
#pragma unroll
            for (int kt = 0; kt < 4; kt++) {
                int off = (mbase + (t & 15)) * 72 + kt * 16 + (t >> 4) * 8;
                ldsm4(qh[kt], sptr(&Ksh[off]));
                ldsm4(ql[kt], sptr(&Ksl[off]));
            }
        }
    }

    float ctx[8][4];
#pragma unroll
    for (int i = 0; i < 8; i++)
#pragma unroll
        for (int q = 0; q < 4; q++) ctx[i][q] = 0.f;
    float m0 = -1e30f, m1 = -1e30f, l0 = 0.f, l1 = 0.f;

    const int ig0 = i0 + w * 16 + g;
    const int ig1 = ig0 + 8;
    const size_t row0  = ((size_t)p * LL + ig0) * LL;
    const size_t row0b = row0 + LL;
    const size_t row1  = ((size_t)p * LL + ig1) * LL;
    const size_t row1b = row1 + LL;

    for (int jt = 0; jt < LL / 64; jt++) {
        const int j0 = jt * 64;
        __syncthreads();
        // ---- stage K/V tiles (64x64) + mask bias ----
#pragma unroll
        for (int s = 0; s < 2; s++) {
            int idx = tid + 256 * s;
            int row = idx >> 3, dq = (idx & 7) * 8;
            const float* base = g_qkv + (size_t)(b * LL + j0 + row) * NQKV + h * 64 + dq;
            float4 k0 = *(const float4*)(base + DM), k1 = *(const float4*)(base + DM + 4);
            uint32_t hh[4], ll[4];
            split2(k0.x, k0.y, hh[0], ll[0]); split2(k0.z, k0.w, hh[1], ll[1]);
            split2(k1.x, k1.y, hh[2], ll[2]); split2(k1.z, k1.w, hh[3], ll[3]);
            *(uint4*)(&Ksh[row * 72 + dq]) = make_uint4(hh[0], hh[1], hh[2], hh[3]);
            *(uint4*)(&Ksl[row * 72 + dq]) = make_uint4(ll[0], ll[1], ll[2], ll[3]);
            float4 v0 = *(const float4*)(base + 2 * DM), v1 = *(const float4*)(base + 2 * DM + 4);
            split2(v0.x, v0.y, hh[0], ll[0]); split2(v0.z, v0.w, hh[1], ll[1]);
            split2(v1.x, v1.y, hh[2], ll[2]); split2(v1.z, v1.w, hh[3], ll[3]);
            *(uint4*)(&Vsh[row * 72 + dq]) = make_uint4(hh[0], hh[1], hh[2], hh[3]);
            *(uint4*)(&Vsl[row * 72 + dq]) = make_uint4(ll[0], ll[1], ll[2], ll[3]);
        }
        if (tid < 64) mb[tid] = g_mask[b * LL + j0 + tid] ? -1e30f : 0.f;
        __syncthreads();

        // ---- S = Qrw . K^T  (8 j-tiles of 8) ----
        float sv[8][4];
#pragma unroll
        for (int i = 0; i < 8; i++)
#pragma unroll
            for (int q = 0; q < 4; q++) sv[i][q] = 0.f;
#pragma unroll
        for (int kt = 0; kt < 4; kt++) {
#pragma unroll
            for (int np = 0; np < 4; np++) {
                uint32_t bh[4], bl[4];
                int nrow = np * 16 + ((t >> 4) << 3) + (t & 7);
                int kcol = kt * 16 + ((t >> 3) & 1) * 8;
                ldsm4(bh, sptr(&Ksh[nrow * 72 + kcol]));
                ldsm4(bl, sptr(&Ksl[nrow * 72 + kcol]));
                mma_bf16(sv[2*np],   qh[kt], bh[0], bh[1]);
                mma_bf16(sv[2*np],   ql[kt], bh[0], bh[1]);
                mma_bf16(sv[2*np],   qh[kt], bl[0], bl[1]);
                mma_bf16(sv[2*np+1], qh[kt], bh[2], bh[3]);
                mma_bf16(sv[2*np+1], ql[kt], bh[2], bh[3]);
                mma_bf16(sv[2*np+1], qh[kt], bl[2], bl[3]);
            }
        }

        // ---- + shifted BD, scale, mask ----
#pragma unroll
        for (int nt = 0; nt < 8; nt++) {
#pragma unroll
            for (int c = 0; c < 2; c++) {
                int jg = j0 + nt * 8 + 2 * tg + c;
                float bd0, bd1;
                if (jg <= ig0)           bd0 = g_bd[row0 + (jg - ig0 + LL - 1)];
                else if (jg == ig0 + 1)  bd0 = 0.f;
                else                     bd0 = g_bd[row0b + (jg - ig0 - 2)];
                if (jg <= ig1)           bd1 = g_bd[row1 + (jg - ig1 + LL - 1)];
                else if (jg == ig1 + 1)  bd1 = 0.f;
                else                     bd1 = g_bd[row1b + (jg - ig1 - 2)];
                float mbj = mb[nt * 8 + 2 * tg + c];
                sv[nt][c]     = (sv[nt][c]     + bd0) * SCALE + mbj;
                sv[nt][c + 2] = (sv[nt][c + 2] + bd1) * SCALE + mbj;
            }
        }

        // ---- online softmax (rows ig0, ig1 per thread; reduce over 4-lane group) --
        float r0m = -1e30f, r1m = -1e30f;
#pragma unroll
        for (int nt = 0; nt < 8; nt++) {
            r0m = fmaxf(r0m, fmaxf(sv[nt][0], sv[nt][1]));
            r1m = fmaxf(r1m, fmaxf(sv[nt][2], sv[nt][3]));
        }
        r0m = fmaxf(r0m, __shfl_xor_sync(0xffffffffu, r0m, 1));
        r0m = fmaxf(r0m, __shfl_xor_sync(0xffffffffu, r0m, 2));
        r1m = fmaxf(r1m, __shfl_xor_sync(0xffffffffu, r1m, 1));
        r1m = fmaxf(r1m, __shfl_xor_sync(0xffffffffu, r1m, 2));
        float m0n = fmaxf(m0, r0m), m1n = fmaxf(m1, r1m);
        float f0 = __expf(m0 - m0n), f1 = __expf(m1 - m1n);
        m0 = m0n; m1 = m1n;
        float ps0 = 0.f, ps1 = 0.f;
#pragma unroll
        for (int nt = 0; nt < 8; nt++) {
            sv[nt][0] = __expf(sv[nt][0] - m0n); ps0 += sv[nt][0];
            sv[nt][1] = __expf(sv[nt][1] - m0n); ps0 += sv[nt][1];
            sv[nt][2] = __expf(sv[nt][2] - m1n); ps1 += sv[nt][2];
            sv[nt][3] = __expf(sv[nt][3] - m1n); ps1 += sv[nt][3];
        }
        ps0 += __shfl_xor_sync(0xffffffffu, ps0, 1);
        ps0 += __shfl_xor_sync(0xffffffffu, ps0, 2);
        ps1 += __shfl_xor_sync(0xffffffffu, ps1, 1);
        ps1 += __shfl_xor_sync(0xffffffffu, ps1, 2);
        l0 = l0 * f0 + ps0;
        l1 = l1 * f1 + ps1;
#pragma unroll
        for (int dt = 0; dt < 8; dt++) {
            ctx[dt][0] *= f0; ctx[dt][1] *= f0;
            ctx[dt][2] *= f1; ctx[dt][3] *= f1;
        }

        // ---- ctx += P @ V  (P frags straight from S frags) ----
#pragma unroll
        for (int kt = 0; kt < 4; kt++) {
            uint32_t ph[4], pl[4];
            split2(sv[2*kt][0],   sv[2*kt][1],   ph[0], pl[0]);
            split2(sv[2*kt][2],   sv[2*kt][3],   ph[1], pl[1]);
            split2(sv[2*kt+1][0], sv[2*kt+1][1], ph[2], pl[2]);
            split2(sv[2*kt+1][2], sv[2*kt+1][3], ph[3], pl[3]);
#pragma unroll
            for (int dp = 0; dp < 4; dp++) {
                uint32_t bh[4], bl[4];
                int off = (kt * 16 + (t & 15)) * 72 + dp * 16 + (t >> 4) * 8;
                ldsm4t(bh, sptr(&Vsh[off]));
                ldsm4t(bl, sptr(&Vsl[off]));
                mma_bf16(ctx[2*dp],   ph, bh[0], bh[1]);
                mma_bf16(ctx[2*dp],   pl, bh[0], bh[1]);
                mma_bf16(ctx[2*dp],   ph, bl[0], bl[1]);
                mma_bf16(ctx[2*dp+1], ph, bh[2], bh[3]);
                mma_bf16(ctx[2*dp+1], pl, bh[2], bh[3]);
                mma_bf16(ctx[2*dp+1], ph, bl[2], bl[3]);
            }
        }
    }

    // ---- epilogue: normalize + store ----
    float inv0 = 1.0f / l0, inv1 = 1.0f / l1;
#pragma unroll
    for (int dt = 0; dt < 8; dt++) {
        int col = h * 64 + dt * 8 + 2 * tg;
        *(float2*)(g_ctx + (size_t)(b * LL + ig0) * DM + col) =
            make_float2(ctx[dt][0] * inv0, ctx[dt][1] * inv0);
        *(float2*)(g_ctx + (size_t)(b * LL + ig1) * DM + col) =
            make_float2(ctx[dt][2] * inv1, ctx[dt][3] * inv1);
    }
}

// ---------------- residual + LayerNorm (unchanged) ------------------------------
__global__ void __launch_bounds__(256) ln_kernel(const float* __restrict__ x,
                                                 const float* __restrict__ gamma,
                                                 const float* __restrict__ beta,
                                                 float* __restrict__ out)
{
    const int row = blockIdx.x;
    const int tid = threadIdx.x;
    __shared__ float yb[DM];
    __shared__ float red[2][8];
    __shared__ float stats[2];

    float4 xv = ((const float4*)(x + (size_t)row * DM))[tid];
    float4 av = ((const float4*)(g_att + (size_t)row * DM))[tid];
    float4 y;
    y.x = xv.x + av.x; y.y = xv.y + av.y; y.z = xv.z + av.z; y.w = xv.w + av.w;
    *(float4*)(&yb[tid * 4]) = y;
    float s  = y.x + y.y + y.z + y.w;
    float sq = y.x * y.x + y.y * y.y + y.z * y.z + y.w * y.w;
#pragma unroll
    for (int off = 16; off >= 1; off >>= 1) {
        s  += __shfl_xor_sync(0xffffffffu, s, off);
        sq += __shfl_xor_sync(0xffffffffu, sq, off);
    }
    if ((tid & 31) == 0) { red[0][tid >> 5] = s; red[1][tid >> 5] = sq; }
    __syncthreads();
    if (tid == 0) {
        float ts = 0.f, tq = 0.f;
#pragma unroll
        for (int q = 0; q < 8; q++) { ts += red[0][q]; tq += red[1][q]; }
        float mu = ts * (1.0f / DM);
        float var = tq * (1.0f / DM) - mu * mu;
        stats[0] = mu;
        stats[1] = rsqrtf(var + LN_EPS);
    }
    __syncthreads();
    float mu = stats[0], inv = stats[1];
    float4 gm = ((const float4*)gamma)[tid];
    float4 be = ((const float4*)beta)[tid];
    float4 yy = *(float4*)(&yb[tid * 4]);
    float4 o;
    o.x = (yy.x - mu) * inv * gm.x + be.x;
    o.y = (yy.y - mu) * inv * gm.y + be.y;
    o.z = (yy.z - mu) * inv * gm.z + be.z;
    o.w = (yy.w - mu) * inv * gm.w + be.w;
    ((float4*)(out + (size_t)row * DM))[tid] = o;
}

// ---------------- launch ---------------------------------------------------------
extern "C" void kernel_launch(void* const* d_in, const int* in_sizes, int n_in,
                              void* d_out, int out_size)
{
    (void)in_sizes; (void)n_in; (void)out_size;
    const float* x      = (const float*)d_in[0];
    const float* relpos = (const float*)d_in[1];
    const float* rwb    = (const float*)d_in[2];
    const float* rrb    = (const float*)d_in[3];
    const void*  maskp  = d_in[4];
    const float* Wqkv   = (const float*)d_in[5];
    const float* Wrel   = (const float*)d_in[6];
    const float* Wout   = (const float*)d_in[7];
    const float* gamma  = (const float*)d_in[8];
    const float* beta   = (const float*)d_in[9];
    float* out = (float*)d_out;

    void *qkvp, *rkp, *ctxp, *attp;
    cudaGetSymbolAddress(&qkvp, g_qkv);
    cudaGetSymbolAddress(&rkp,  g_rk);
    cudaGetSymbolAddress(&ctxp, g_ctx);
    cudaGetSymbolAddress(&attp, g_att);

    const int bd_smem = 4 * 128 * 72 * sizeof(unsigned short);   // 73728
    cudaFuncSetAttribute(bd_bf163, cudaFuncAttributeMaxDynamicSharedMemorySize, bd_smem);

    // 0) normalize mask
    mask_detect<<<1, 256>>>((const unsigned char*)maskp);
    mask_convert<<<(BB * LL + 255) / 256, 256>>>(maskp);

    // 1) QKV = x @ W_qkv
    gemm_bf163<<<dim3(NQKV / 128, (BB * LL) / 128), 256>>>(x, Wqkv, (float*)qkvp, BB * LL, NQKV, DM);
    // 2) RK = relpos @ W_rel
    gemm_bf163<<<dim3(DM / 128, LL / 128), 256>>>(relpos, Wrel, (float*)rkp, LL, DM, DM);
    // 3) BD batched NT GEMMs
    bd_bf163<<<dim3(LL / 128, LL / 128, PAIRS), 256, bd_smem>>>(rrb);
    // 4) flash attention (tensor cores)
    attn_bf163<<<dim3(LL / 128, NH, BB), 256>>>(rwb);
    // 5) attn_out = ctx @ W_out
    gemm_bf163<<<dim3(DM / 128, (BB * LL) / 128), 256>>>((const float*)ctxp, Wout, (float*)attp, BB * LL, DM, DM);
    // 6) residual + layernorm
    ln_kernel<<<BB * LL, 256>>>(x, gamma, beta, out);
}

// round 4
// speedup vs baseline: 1.4482x; 1.0584x over previous
#include <cuda_runtime.h>
#include <cuda_bf16.h>
#include <cstdint>
#include <cstddef>

#define BB 2
#define LL 2048
#define NH 16
#define DH 64
#define DM 1024
#define NQKV 3072
#define PAIRS (BB*NH)
#define SCALE 0.125f
#define LN_EPS 1e-5f

typedef unsigned short ushort_t;

// ---------------- persistent scratch (no allocation) ----------------
__device__ float    g_bd [(size_t)PAIRS*LL*LL];    // 537 MB
__device__ float    g_att[(size_t)BB*LL*DM];
__device__ ushort_t g_xh[(size_t)BB*LL*DM],    g_xl[(size_t)BB*LL*DM];
__device__ ushort_t g_rph[(size_t)LL*DM],      g_rpl[(size_t)LL*DM];
__device__ ushort_t g_wqkvh[(size_t)DM*NQKV],  g_wqkvl[(size_t)DM*NQKV];
__device__ ushort_t g_wrelh[(size_t)DM*DM],    g_wrell[(size_t)DM*DM];
__device__ ushort_t g_wouth[(size_t)DM*DM],    g_woutl[(size_t)DM*DM];
__device__ ushort_t g_qrwh[(size_t)BB*LL*DM],  g_qrwl[(size_t)BB*LL*DM];
__device__ ushort_t g_qrrh[(size_t)BB*LL*DM],  g_qrrl[(size_t)BB*LL*DM];
__device__ ushort_t g_kh[(size_t)BB*LL*DM],    g_kl[(size_t)BB*LL*DM];
__device__ ushort_t g_vh[(size_t)BB*LL*DM],    g_vl[(size_t)BB*LL*DM];
__device__ ushort_t g_rkh[(size_t)LL*DM],      g_rkl[(size_t)LL*DM];
__device__ ushort_t g_ctxh[(size_t)BB*LL*DM],  g_ctxl[(size_t)BB*LL*DM];
__device__ int      g_mask_mode;
__device__ unsigned char g_mask[BB*LL];

// ---------------- helpers ----------------
__device__ __forceinline__ uint32_t sptr(const void* p) {
    return (uint32_t)__cvta_generic_to_shared(p);
}
__device__ __forceinline__ void ldsm4(uint32_t (&r)[4], uint32_t addr) {
    asm volatile("ldmatrix.sync.aligned.m8n8.x4.shared.b16 {%0,%1,%2,%3},[%4];"
        : "=r"(r[0]), "=r"(r[1]), "=r"(r[2]), "=r"(r[3]) : "r"(addr));
}
__device__ __forceinline__ void ldsm4t(uint32_t (&r)[4], uint32_t addr) {
    asm volatile("ldmatrix.sync.aligned.m8n8.x4.trans.shared.b16 {%0,%1,%2,%3},[%4];"
        : "=r"(r[0]), "=r"(r[1]), "=r"(r[2]), "=r"(r[3]) : "r"(addr));
}
__device__ __forceinline__ void mma_bf16(float* d, const uint32_t* a, uint32_t b0, uint32_t b1) {
    asm volatile("mma.sync.aligned.m16n8k16.row.col.f32.bf16.bf16.f32 "
        "{%0,%1,%2,%3},{%4,%5,%6,%7},{%8,%9},{%0,%1,%2,%3};"
        : "+f"(d[0]), "+f"(d[1]), "+f"(d[2]), "+f"(d[3])
        : "r"(a[0]), "r"(a[1]), "r"(a[2]), "r"(a[3]), "r"(b0), "r"(b1));
}
__device__ __forceinline__ void split2(float x, float y, uint32_t& h, uint32_t& l) {
    __nv_bfloat162 hv = __floats2bfloat162_rn(x, y);
    float2 hf = __bfloat1622float2(hv);
    __nv_bfloat162 lv = __floats2bfloat162_rn(x - hf.x, y - hf.y);
    h = *reinterpret_cast<uint32_t*>(&hv);
    l = *reinterpret_cast<uint32_t*>(&lv);
}
__device__ __forceinline__ void cpa16(uint32_t dst, const void* src) {
    asm volatile("cp.async.cg.shared.global [%0],[%1],16;" :: "r"(dst), "l"(src));
}
__device__ __forceinline__ void cpa_commit() {
    asm volatile("cp.async.commit_group;");
}

// ---------------- pre-split fp32 -> bf16 hi/lo planes ----------------
__global__ void split_planes(const float* __restrict__ in,
                             ushort_t* __restrict__ oh, ushort_t* __restrict__ ol, int n)
{
    int i = (blockIdx.x * blockDim.x + threadIdx.x) * 2;
    if (i >= n) return;
    uint32_t h, l;
    split2(in[i], in[i + 1], h, l);
    *(uint32_t*)(oh + i) = h;
    *(uint32_t*)(ol + i) = l;
}

// ---------------- mask sniff + normalize (proven) ----------------
__global__ void mask_detect(const unsigned char* __restrict__ m) {
    __shared__ int flag_off4, flag_big;
    if (threadIdx.x == 0) { flag_off4 = 0; flag_big = 0; }
    __syncthreads();
    int lo = 0, lb = 0;
    for (int i = threadIdx.x; i < BB * LL; i += blockDim.x) {
        unsigned char v = m[i];
        if (v != 0 && (i & 3) != 0) lo = 1;
        if (v > 1) lb = 1;
    }
    if (lo) atomicOr(&flag_off4, 1);
    if (lb) atomicOr(&flag_big, 1);
    __syncthreads();
    if (threadIdx.x == 0) g_mask_mode = lb || flag_big ? (flag_big ? 2 : 2) : 0, // placeholder
        g_mask_mode = flag_big ? 2 : (flag_off4 ? 0 : 1);
}
__global__ void mask_convert(const void* __restrict__ m) {
    int i = blockIdx.x * blockDim.x + threadIdx.x;
    if (i >= BB * LL) return;
    int mode = g_mask_mode;
    unsigned char r;
    if (mode == 0)      r = ((const unsigned char*)m)[i] != 0;
    else if (mode == 1) r = ((const int*)m)[i] != 0;
    else                r = ((const float*)m)[i] != 0.0f;
    g_mask[i] = r;
}

// ================================================================================
// GEMM NN on pre-split bf16 planes. C = A @ B. Block 128x128, BK=32, 256 thr,
// cp.async double-buffered. MODE 0: fp32 C. MODE 1: hi/lo plane C. MODE 2: QKV
// routing epilogue (q+rwb -> qrw planes, q+rrb -> qrr planes, k, v planes).
// ================================================================================
template <int MODE>
__global__ void __launch_bounds__(256, 2) gemm_v2(
    const ushort_t* __restrict__ Ahg, const ushort_t* __restrict__ Alg,
    const ushort_t* __restrict__ Bhg, const ushort_t* __restrict__ Blg,
    float* __restrict__ C,
    ushort_t* __restrict__ Ch, ushort_t* __restrict__ Cl,
    const float* __restrict__ rwb, const float* __restrict__ rrb,
    int M, int N, int K)
{
    extern __shared__ ushort_t sm[];
    ushort_t* AH = sm;                    // 2 x 128 x 40
    ushort_t* AL = AH + 2 * 128 * 40;
    ushort_t* BH = AL + 2 * 128 * 40;     // 2 x 32 x 136
    ushort_t* BL = BH + 2 * 32 * 136;

    const int tid = threadIdx.x, w = tid >> 5, t = tid & 31;
    const int m0 = blockIdx.y * 128, n0 = blockIdx.x * 128;
    const int wm = (w >> 2) * 64, wn = (w & 3) * 32;
    const int g = t >> 2, tg = t & 3;

    float d[4][4][4];
#pragma unroll
    for (int i = 0; i < 4; i++)
#pragma unroll
        for (int j = 0; j < 4; j++)
#pragma unroll
            for (int q = 0; q < 4; q++) d[i][j][q] = 0.f;

    const int nk = K / 32;
    // stage issue lambda
    auto issue = [&](int kb, int buf) {
#pragma unroll
        for (int s = 0; s < 2; s++) {
            int idx = tid + 256 * s;
            int row = idx >> 2, seg = (idx & 3) * 8;
            size_t src = (size_t)(m0 + row) * K + kb * 32 + seg;
            uint32_t da = sptr(AH + buf * 5120 + row * 40 + seg);
            cpa16(da, Ahg + src);
            cpa16(da + (uint32_t)((AL - AH) * 2), Alg + src);
        }
#pragma unroll
        for (int s = 0; s < 2; s++) {
            int idx = tid + 256 * s;
            int row = idx >> 4, seg = (idx & 15) * 8;
            size_t src = (size_t)(kb * 32 + row) * N + n0 + seg;
            uint32_t db = sptr(BH + buf * 4352 + row * 136 + seg);
            cpa16(db, Bhg + src);
            cpa16(db + (uint32_t)((BL - BH) * 2), Blg + src);
        }
        cpa_commit();
    };

    issue(0, 0);
    for (int kb = 0; kb < nk; kb++) {
        const int buf = kb & 1;
        if (kb + 1 < nk) {
            issue(kb + 1, buf ^ 1);
            asm volatile("cp.async.wait_group 1;");
        } else {
            asm volatile("cp.async.wait_group 0;");
        }
        __syncthreads();

        const ushort_t* ah_b = AH + buf * 5120;
        const ushort_t* al_b = AL + buf * 5120;
        const ushort_t* bh_b = BH + buf * 4352;
        const ushort_t* bl_b = BL + buf * 4352;
#pragma unroll
        for (int kt = 0; kt < 2; kt++) {
            uint32_t ah[4][4], al[4][4];
#pragma unroll
            for (int mt = 0; mt < 4; mt++) {
                int off = (wm + mt * 16 + (t & 15)) * 40 + kt * 16 + (t >> 4) * 8;
                ldsm4(ah[mt], sptr(ah_b + off));
                ldsm4(al[mt], sptr(al_b + off));
            }
#pragma unroll
            for (int np = 0; np < 2; np++) {
                uint32_t bh[4], bl[4];
                int off = (kt * 16 + (t & 15)) * 136 + wn + np * 16 + (t >> 4) * 8;
                ldsm4t(bh, sptr(bh_b + off));
                ldsm4t(bl, sptr(bl_b + off));
#pragma unroll
                for (int mt = 0; mt < 4; mt++) {
                    mma_bf16(d[mt][2*np],   ah[mt], bh[0], bh[1]);
                    mma_bf16(d[mt][2*np],   al[mt], bh[0], bh[1]);
                    mma_bf16(d[mt][2*np],   ah[mt], bl[0], bl[1]);
                    mma_bf16(d[mt][2*np+1], ah[mt], bh[2], bh[3]);
                    mma_bf16(d[mt][2*np+1], al[mt], bh[2], bh[3]);
                    mma_bf16(d[mt][2*np+1], ah[mt], bl[2], bl[3]);
                }
            }
        }
        __syncthreads();
    }

    // ---- epilogue ----
#pragma unroll
    for (int mt = 0; mt < 4; mt++) {
#pragma unroll
        for (int nt = 0; nt < 4; nt++) {
            int row = m0 + wm + mt * 16 + g;
            int col = n0 + wn + nt * 8 + 2 * tg;
            if (MODE == 0) {
                *(float2*)(C + (size_t)row * N + col)       = make_float2(d[mt][nt][0], d[mt][nt][1]);
                *(float2*)(C + (size_t)(row + 8) * N + col) = make_float2(d[mt][nt][2], d[mt][nt][3]);
            } else if (MODE == 1) {
                uint32_t h, l;
                split2(d[mt][nt][0], d[mt][nt][1], h, l);
                *(uint32_t*)(Ch + (size_t)row * N + col) = h;
                *(uint32_t*)(Cl + (size_t)row * N + col) = l;
                split2(d[mt][nt][2], d[mt][nt][3], h, l);
                *(uint32_t*)(Ch + (size_t)(row + 8) * N + col) = h;
                *(uint32_t*)(Cl + (size_t)(row + 8) * N + col) = l;
            } else {
                int sec = col >> 10;          // uniform per block (128 | 1024)
                int cl  = col & 1023;
                size_t o0 = (size_t)row * DM + cl;
                size_t o1 = (size_t)(row + 8) * DM + cl;
                uint32_t h, l;
                if (sec == 0) {
                    float b0 = rwb[cl], b1 = rwb[cl + 1];
                    float c0 = rrb[cl], c1 = rrb[cl + 1];
                    split2(d[mt][nt][0] + b0, d[mt][nt][1] + b1, h, l);
                    *(uint32_t*)(g_qrwh + o0) = h; *(uint32_t*)(g_qrwl + o0) = l;
                    split2(d[mt][nt][2] + b0, d[mt][nt][3] + b1, h, l);
                    *(uint32_t*)(g_qrwh + o1) = h; *(uint32_t*)(g_qrwl + o1) = l;
                    split2(d[mt][nt][0] + c0, d[mt][nt][1] + c1, h, l);
                    *(uint32_t*)(g_qrrh + o0) = h; *(uint32_t*)(g_qrrl + o0) = l;
                    split2(d[mt][nt][2] + c0, d[mt][nt][3] + c1, h, l);
                    *(uint32_t*)(g_qrrh + o1) = h; *(uint32_t*)(g_qrrl + o1) = l;
                } else if (sec == 1) {
                    split2(d[mt][nt][0], d[mt][nt][1], h, l);
                    *(uint32_t*)(g_kh + o0) = h; *(uint32_t*)(g_kl + o0) = l;
                    split2(d[mt][nt][2], d[mt][nt][3], h, l);
                    *(uint32_t*)(g_kh + o1) = h; *(uint32_t*)(g_kl + o1) = l;
                } else {
                    split2(d[mt][nt][0], d[mt][nt][1], h, l);
                    *(uint32_t*)(g_vh + o0) = h; *(uint32_t*)(g_vl + o0) = l;
                    split2(d[mt][nt][2], d[mt][nt][3], h, l);
                    *(uint32_t*)(g_vh + o1) = h; *(uint32_t*)(g_vl + o1) = l;
                }
            }
        }
    }
}

// ================================================================================
// BD NT GEMM on planes: BD[p,i,r] = qrr[b,i,h,:] . rk[r,h,:],  K=64 one shot.
// ================================================================================
__global__ void __launch_bounds__(256) bd_v2()
{
    extern __shared__ ushort_t sm2[];
    ushort_t* Ahs = sm2;                  // 128 x 72
    ushort_t* Als = Ahs + 128 * 72;
    ushort_t* Bhs = Als + 128 * 72;
    ushort_t* Bls = Bhs + 128 * 72;

    const int p = blockIdx.z, b = p >> 4, h = p & 15;
    const int i0 = blockIdx.y * 128, r0 = blockIdx.x * 128;
    const int tid = threadIdx.x, w = tid >> 5, t = tid & 31;
    const int wm = (w >> 2) * 64, wn = (w & 3) * 32;
    const int g = t >> 2, tg = t & 3;

#pragma unroll
    for (int s = 0; s < 4; s++) {
        int idx = tid + 256 * s;
        int row = idx >> 3, dq = (idx & 7) * 8;
        size_t srcA = (size_t)(b * LL + i0 + row) * DM + h * 64 + dq;
        *(uint4*)(&Ahs[row * 72 + dq]) = *(const uint4*)(g_qrrh + srcA);
        *(uint4*)(&Als[row * 72 + dq]) = *(const uint4*)(g_qrrl + srcA);
        size_t srcB = (size_t)(r0 + row) * DM + h * 64 + dq;
        *(uint4*)(&Bhs[row * 72 + dq]) = *(const uint4*)(g_rkh + srcB);
        *(uint4*)(&Bls[row * 72 + dq]) = *(const uint4*)(g_rkl + srcB);
    }
    __syncthreads();

    float d[4][4][4];
#pragma unroll
    for (int i = 0; i < 4; i++)
#pragma unroll
        for (int j = 0; j < 4; j++)
#pragma unroll
            for (int q = 0; q < 4; q++) d[i][j][q] = 0.f;

#pragma unroll
    for (int kt = 0; kt < 4; kt++) {
        uint32_t ah[4][4], al[4][4];
#pragma unroll
        for (int mt = 0; mt < 4; mt++) {
            int off = (wm + mt * 16 + (t & 15)) * 72 + kt * 16 + (t >> 4) * 8;
            ldsm4(ah[mt], sptr(&Ahs[off]));
            ldsm4(al[mt], sptr(&Als[off]));
        }
#pragma unroll
        for (int np = 0; np < 2; np++) {
            uint32_t bh[4], bl[4];
            int nrow = wn + np * 16 + ((t >> 4) << 3) + (t & 7);
            int kcol = kt * 16 + ((t >> 3) & 1) * 8;
            ldsm4(bh, sptr(&Bhs[nrow * 72 + kcol]));
            ldsm4(bl, sptr(&Bls[nrow * 72 + kcol]));
#pragma unroll
            for (int mt = 0; mt < 4; mt++) {
                mma_bf16(d[mt][2*np],   ah[mt], bh[0], bh[1]);
                mma_bf16(d[mt][2*np],   al[mt], bh[0], bh[1]);
                mma_bf16(d[mt][2*np],   ah[mt], bl[0], bl[1]);
                mma_bf16(d[mt][2*np+1], ah[mt], bh[2], bh[3]);
                mma_bf16(d[mt][2*np+1], al[mt], bh[2], bh[3]);
                mma_bf16(d[mt][2*np+1], ah[mt], bl[2], bl[3]);
            }
        }
    }
#pragma unroll
    for (int mt = 0; mt < 4; mt++) {
#pragma unroll
        for (int nt = 0; nt < 4; nt++) {
            int row = i0 + wm + mt * 16 + g;
            int col = r0 + wn + nt * 8 + 2 * tg;
            *(float2*)(g_bd + ((size_t)p * LL + row) * LL + col)     = make_float2(d[mt][nt][0], d[mt][nt][1]);
            *(float2*)(g_bd + ((size_t)p * LL + row + 8) * LL + col) = make_float2(d[mt][nt][2], d[mt][nt][3]);
        }
    }
}

// ================================================================================
// Flash attention on planes.  Block = 128 q-rows x (b,h); 8 warps.
// ================================================================================
__global__ void __launch_bounds__(256) attn_v2()
{
    __shared__ __align__(16) ushort_t Ksh[64*72], Ksl[64*72];
    __shared__ __align__(16) ushort_t Vsh[64*72], Vsl[64*72];
    __shared__ float mb[64];

    const int it = blockIdx.x, h = blockIdx.y, b = blockIdx.z;
    const int i0 = it * 128;
    const int p = b * NH + h;
    const int tid = threadIdx.x, w = tid >> 5, t = tid & 31;
    const int g = t >> 2, tg = t & 3;

    // Q prologue: stage halves through Ks, grab frags
    uint32_t qh[4][4], ql[4][4];
#pragma unroll
    for (int half = 0; half < 2; half++) {
        __syncthreads();
#pragma unroll
        for (int s = 0; s < 2; s++) {
            int idx = tid + 256 * s;
            int row = idx >> 3, dq = (idx & 7) * 8;
            size_t src = (size_t)(b * LL + i0 + half * 64 + row) * DM + h * 64 + dq;
            *(uint4*)(&Ksh[row * 72 + dq]) = *(const uint4*)(g_qrwh + src);
            *(uint4*)(&Ksl[row * 72 + dq]) = *(const uint4*)(g_qrwl + src);
        }
        __syncthreads();
        if ((w >> 2) == half) {
            int mbase = (w & 3) * 16;
#pragma unroll
            for (int kt = 0; kt < 4; kt++) {
                int off = (mbase + (t & 15)) * 72 + kt * 16 + (t >> 4) * 8;
                ldsm4(qh[kt], sptr(&Ksh[off]));
                ldsm4(ql[kt], sptr(&Ksl[off]));
            }
        }
    }

    float ctx[8][4];
#pragma unroll
    for (int i = 0; i < 8; i++)
#pragma unroll
        for (int q = 0; q < 4; q++) ctx[i][q] = 0.f;
    float m0 = -1e30f, m1 = -1e30f, l0 = 0.f, l1 = 0.f;

    const int ig0 = i0 + w * 16 + g;
    const int ig1 = ig0 + 8;
    const size_t row0  = ((size_t)p * LL + ig0) * LL;
    const size_t row0b = row0 + LL;
    const size_t row1  = ((size_t)p * LL + ig1) * LL;
    const size_t row1b = row1 + LL;

    for (int jt = 0; jt < LL / 64; jt++) {
        const int j0 = jt * 64;
        __syncthreads();
#pragma unroll
        for (int s = 0; s < 2; s++) {
            int idx = tid + 256 * s;
            int row = idx >> 3, dq = (idx & 7) * 8;
            size_t src = (size_t)(b * LL + j0 + row) * DM + h * 64 + dq;
            *(uint4*)(&Ksh[row * 72 + dq]) = *(const uint4*)(g_kh + src);
            *(uint4*)(&Ksl[row * 72 + dq]) = *(const uint4*)(g_kl + src);
            *(uint4*)(&Vsh[row * 72 + dq]) = *(const uint4*)(g_vh + src);
            *(uint4*)(&Vsl[row * 72 + dq]) = *(const uint4*)(g_vl + src);
        }
        if (tid < 64) mb[tid] = g_mask[b * LL + j0 + tid] ? -1e30f : 0.f;
        __syncthreads();

        // S = Qrw . K^T
        float sv[8][4];
#pragma unroll
        for (int i = 0; i < 8; i++)
#pragma unroll
            for (int q = 0; q < 4; q++) sv[i][q] = 0.f;
#pragma unroll
        for (int kt = 0; kt < 4; kt++) {
#pragma unroll
            for (int np = 0; np < 4; np++) {
                uint32_t bh[4], bl[4];
                int nrow = np * 16 + ((t >> 4) << 3) + (t & 7);
                int kcol = kt * 16 + ((t >> 3) & 1) * 8;
                ldsm4(bh, sptr(&Ksh[nrow * 72 + kcol]));
                ldsm4(bl, sptr(&Ksl[nrow * 72 + kcol]));
                mma_bf16(sv[2*np],   qh[kt], bh[0], bh[1]);
                mma_bf16(sv[2*np],   ql[kt], bh[0], bh[1]);
                mma_bf16(sv[2*np],   qh[kt], bl[0], bl[1]);
                mma_bf16(sv[2*np+1], qh[kt], bh[2], bh[3]);
                mma_bf16(sv[2*np+1], ql[kt], bh[2], bh[3]);
                mma_bf16(sv[2*np+1], qh[kt], bl[2], bl[3]);
            }
        }

        // + shifted BD, scale, mask
#pragma unroll
        for (int nt = 0; nt < 8; nt++) {
#pragma unroll
            for (int c = 0; c < 2; c++) {
                int jg = j0 + nt * 8 + 2 * tg + c;
                float bd0, bd1;
                if (jg <= ig0)           bd0 = g_bd[row0 + (jg - ig0 + LL - 1)];
                else if (jg == ig0 + 1)  bd0 = 0.f;
                else                     bd0 = g_bd[row0b + (jg - ig0 - 2)];
                if (jg <= ig1)           bd1 = g_bd[row1 + (jg - ig1 + LL - 1)];
                else if (jg == ig1 + 1)  bd1 = 0.f;
                else                     bd1 = g_bd[row1b + (jg - ig1 - 2)];
                float mbj = mb[nt * 8 + 2 * tg + c];
                sv[nt][c]     = (sv[nt][c]     + bd0) * SCALE + mbj;
                sv[nt][c + 2] = (sv[nt][c + 2] + bd1) * SCALE + mbj;
            }
        }

        // online softmax
        float r0m = -1e30f, r1m = -1e30f;
#pragma unroll
        for (int nt = 0; nt < 8; nt++) {
            r0m = fmaxf(r0m, fmaxf(sv[nt][0], sv[nt][1]));
            r1m = fmaxf(r1m, fmaxf(sv[nt][2], sv[nt][3]));
        }
        r0m = fmaxf(r0m, __shfl_xor_sync(0xffffffffu, r0m, 1));
        r0m = fmaxf(r0m, __shfl_xor_sync(0xffffffffu, r0m, 2));
        r1m = fmaxf(r1m, __shfl_xor_sync(0xffffffffu, r1m, 1));
        r1m = fmaxf(r1m, __shfl_xor_sync(0xffffffffu, r1m, 2));
        float m0n = fmaxf(m0, r0m), m1n = fmaxf(m1, r1m);
        float f0 = __expf(m0 - m0n), f1 = __expf(m1 - m1n);
        m0 = m0n; m1 = m1n;
        float ps0 = 0.f, ps1 = 0.f;
#pragma unroll
        for (int nt = 0; nt < 8; nt++) {
            sv[nt][0] = __expf(sv[nt][0] - m0n); ps0 += sv[nt][0];
            sv[nt][1] = __expf(sv[nt][1] - m0n); ps0 += sv[nt][1];
            sv[nt][2] = __expf(sv[nt][2] - m1n); ps1 += sv[nt][2];
            sv[nt][3] = __expf(sv[nt][3] - m1n); ps1 += sv[nt][3];
        }
        ps0 += __shfl_xor_sync(0xffffffffu, ps0, 1);
        ps0 += __shfl_xor_sync(0xffffffffu, ps0, 2);
        ps1 += __shfl_xor_sync(0xffffffffu, ps1, 1);
        ps1 += __shfl_xor_sync(0xffffffffu, ps1, 2);
        l0 = l0 * f0 + ps0;
        l1 = l1 * f1 + ps1;
#pragma unroll
        for (int dt = 0; dt < 8; dt++) {
            ctx[dt][0] *= f0; ctx[dt][1] *= f0;
            ctx[dt][2] *= f1; ctx[dt][3] *= f1;
        }

        // ctx += P @ V
#pragma unroll
        for (int kt = 0; kt < 4; kt++) {
            uint32_t ph[4], pl[4];
            split2(sv[2*kt][0],   sv[2*kt][1],   ph[0], pl[0]);
            split2(sv[2*kt][2],   sv[2*kt][3],   ph[1], pl[1]);
            split2(sv[2*kt+1][0], sv[2*kt+1][1], ph[2], pl[2]);
            split2(sv[2*kt+1][2], sv[2*kt+1][3], ph[3], pl[3]);
#pragma unroll
            for (int dp = 0; dp < 4; dp++) {
                uint32_t bh[4], bl[4];
                int off = (kt * 16 + (t & 15)) * 72 + dp * 16 + (t >> 4) * 8;
                ldsm4t(bh, sptr(&Vsh[off]));
                ldsm4t(bl, sptr(&Vsl[off]));
                mma_bf16(ctx[2*dp],   ph, bh[0], bh[1]);
                mma_bf16(ctx[2*dp],   pl, bh[0], bh[1]);
                mma_bf16(ctx[2*dp],   ph, bl[0], bl[1]);
                mma_bf16(ctx[2*dp+1], ph, bh[2], bh[3]);
                mma_bf16(ctx[2*dp+1], pl, bh[2], bh[3]);
                mma_bf16(ctx[2*dp+1], ph, bl[2], bl[3]);
            }
        }
    }

    // epilogue: normalize + emit hi/lo planes for the W_out GEMM
    float inv0 = 1.0f / l0, inv1 = 1.0f / l1;
#pragma unroll
    for (int dt = 0; dt < 8; dt++) {
        int col = h * 64 + dt * 8 + 2 * tg;
        size_t o0 = (size_t)(b * LL + ig0) * DM + col;
        size_t o1 = (size_t)(b * LL + ig1) * DM + col;
        uint32_t hh, ll;
        split2(ctx[dt][0] * inv0, ctx[dt][1] * inv0, hh, ll);
        *(uint32_t*)(g_ctxh + o0) = hh; *(uint32_t*)(g_ctxl + o0) = ll;
        split2(ctx[dt][2] * inv1, ctx[dt][3] * inv1, hh, ll);
        *(uint32_t*)(g_ctxh + o1) = hh; *(uint32_t*)(g_ctxl + o1) = ll;
    }
}

// ---------------- residual + LayerNorm ----------------
__global__ void __launch_bounds__(256) ln_kernel(const float* __restrict__ x,
                                                 const float* __restrict__ gamma,
                                                 const float* __restrict__ beta,
                                                 float* __restrict__ out)
{
    const int row = blockIdx.x;
    const int tid = threadIdx.x;
    __shared__ float yb[DM];
    __shared__ float red[2][8];
    __shared__ float stats[2];

    float4 xv = ((const float4*)(x + (size_t)row * DM))[tid];
    float4 av = ((const float4*)(g_att + (size_t)row * DM))[tid];
    float4 y;
    y.x = xv.x + av.x; y.y = xv.y + av.y; y.z = xv.z + av.z; y.w = xv.w + av.w;
    *(float4*)(&yb[tid * 4]) = y;
    float s  = y.x + y.y + y.z + y.w;
    float sq = y.x * y.x + y.y * y.y + y.z * y.z + y.w * y.w;
#pragma unroll
    for (int off = 16; off >= 1; off >>= 1) {
        s  += __shfl_xor_sync(0xffffffffu, s, off);
        sq += __shfl_xor_sync(0xffffffffu, sq, off);
    }
    if ((tid & 31) == 0) { red[0][tid >> 5] = s; red[1][tid >> 5] = sq; }
    __syncthreads();
    if (tid == 0) {
        float ts = 0.f, tq = 0.f;
#pragma unroll
        for (int q = 0; q < 8; q++) { ts += red[0][q]; tq += red[1][q]; }
        float mu = ts * (1.0f / DM);
        float var = tq * (1.0f / DM) - mu * mu;
        stats[0] = mu;
        stats[1] = rsqrtf(var + LN_EPS);
    }
    __syncthreads();
    float mu = stats[0], inv = stats[1];
    float4 gm = ((const float4*)gamma)[tid];
    float4 be = ((const float4*)beta)[tid];
    float4 yy = *(float4*)(&yb[tid * 4]);
    float4 o;
    o.x = (yy.x - mu) * inv * gm.x + be.x;
    o.y = (yy.y - mu) * inv * gm.y + be.y;
    o.z = (yy.z - mu) * inv * gm.z + be.z;
    o.w = (yy.w - mu) * inv * gm.w + be.w;
    ((float4*)(out + (size_t)row * DM))[tid] = o;
}

// ---------------- launch ----------------
extern "C" void kernel_launch(void* const* d_in, const int* in_sizes, int n_in,
                              void* d_out, int out_size)
{
    (void)in_sizes; (void)n_in; (void)out_size;
    const float* x      = (const float*)d_in[0];
    const float* relpos = (const float*)d_in[1];
    const float* rwb    = (const float*)d_in[2];
    const float* rrb    = (const float*)d_in[3];
    const void*  maskp  = d_in[4];
    const float* Wqkv   = (const float*)d_in[5];
    const float* Wrel   = (const float*)d_in[6];
    const float* Wout   = (const float*)d_in[7];
    const float* gamma  = (const float*)d_in[8];
    const float* beta   = (const float*)d_in[9];
    float* out = (float*)d_out;

    ushort_t *xh, *xl, *rph, *rpl, *wqh, *wql, *wrh, *wrl, *woh, *wol;
    ushort_t *rkh, *rkl, *cth, *ctl;
    float* attp;
    cudaGetSymbolAddress((void**)&xh,  g_xh);   cudaGetSymbolAddress((void**)&xl,  g_xl);
    cudaGetSymbolAddress((void**)&rph, g_rph);  cudaGetSymbolAddress((void**)&rpl, g_rpl);
    cudaGetSymbolAddress((void**)&wqh, g_wqkvh);cudaGetSymbolAddress((void**)&wql, g_wqkvl);
    cudaGetSymbolAddress((void**)&wrh, g_wrelh);cudaGetSymbolAddress((void**)&wrl, g_wrell);
    cudaGetSymbolAddress((void**)&woh, g_wouth);cudaGetSymbolAddress((void**)&wol, g_woutl);
    cudaGetSymbolAddress((void**)&rkh, g_rkh);  cudaGetSymbolAddress((void**)&rkl, g_rkl);
    cudaGetSymbolAddress((void**)&cth, g_ctxh); cudaGetSymbolAddress((void**)&ctl, g_ctxl);
    cudaGetSymbolAddress((void**)&attp, g_att);

    const int gemm_smem = (2*128*40 + 2*128*40 + 2*32*136 + 2*32*136) * (int)sizeof(ushort_t); // 75776
    cudaFuncSetAttribute(gemm_v2<0>, cudaFuncAttributeMaxDynamicSharedMemorySize, gemm_smem);
    cudaFuncSetAttribute(gemm_v2<1>, cudaFuncAttributeMaxDynamicSharedMemorySize, gemm_smem);
    cudaFuncSetAttribute(gemm_v2<2>, cudaFuncAttributeMaxDynamicSharedMemorySize, gemm_smem);
    const int bd_smem = 4 * 128 * 72 * (int)sizeof(ushort_t);
    cudaFuncSetAttribute(bd_v2, cudaFuncAttributeMaxDynamicSharedMemorySize, bd_smem);

    // 0) mask + input pre-splits
    mask_detect<<<1, 256>>>((const unsigned char*)maskp);
    mask_convert<<<(BB * LL + 255) / 256, 256>>>(maskp);
    split_planes<<<(BB*LL*DM/2 + 255) / 256, 256>>>(x,      xh,  xl,  BB*LL*DM);
    split_planes<<<(LL*DM/2 + 255) / 256, 256>>>(relpos,    rph, rpl, LL*DM);
    split_planes<<<(DM*NQKV/2 + 255) / 256, 256>>>(Wqkv,    wqh, wql, DM*NQKV);
    split_planes<<<(DM*DM/2 + 255) / 256, 256>>>(Wrel,      wrh, wrl, DM*DM);
    split_planes<<<(DM*DM/2 + 255) / 256, 256>>>(Wout,      woh, wol, DM*DM);

    // 1) QKV with routing epilogue (biases folded, planes emitted)
    gemm_v2<2><<<dim3(NQKV/128, (BB*LL)/128), 256, gemm_smem>>>(
        xh, xl, wqh, wql, nullptr, nullptr, nullptr, rwb, rrb, BB*LL, NQKV, DM);
    // 2) RK planes
    gemm_v2<1><<<dim3(DM/128, LL/128), 256, gemm_smem>>>(
        rph, rpl, wrh, wrl, nullptr, rkh, rkl, nullptr, nullptr, LL, DM, DM);
    // 3) BD
    bd_v2<<<dim3(LL/128, LL/128, PAIRS), 256, bd_smem>>>();
    // 4) flash attention
    attn_v2<<<dim3(LL/128, NH, BB), 256>>>();
    // 5) attn_out = ctx @ W_out (fp32 out)
    gemm_v2<0><<<dim3(DM/128, (BB*LL)/128), 256, gemm_smem>>>(
        cth, ctl, woh, wol, attp, nullptr, nullptr, nullptr, nullptr, BB*LL, DM, DM);
    // 6) residual + layernorm
    ln_kernel<<<BB * LL, 256>>>(x, gamma, beta, out);
}

// round 5
// speedup vs baseline: 2.3490x; 1.6220x over previous
#include <cuda_runtime.h>
#include <cuda_bf16.h>
#include <cstdint>
#include <cstddef>

#define BB 2
#define LL 2048
#define NH 16
#define DH 64
#define DM 1024
#define NQKV 3072
#define PAIRS (BB*NH)
#define SCALE 0.125f
#define LN_EPS 1e-5f
#define MASKV (-8e30f)

typedef unsigned short ushort_t;

// ---------------- persistent scratch (no allocation) ----------------
__device__ float    g_bds[(size_t)PAIRS*LL*LL];    // SHIFTED bd + mask folded, 537 MB
__device__ float    g_att[(size_t)BB*LL*DM];
__device__ ushort_t g_xh[(size_t)BB*LL*DM],    g_xl[(size_t)BB*LL*DM];
__device__ ushort_t g_rph[(size_t)LL*DM],      g_rpl[(size_t)LL*DM];
__device__ ushort_t g_wqkvh[(size_t)DM*NQKV],  g_wqkvl[(size_t)DM*NQKV];
__device__ ushort_t g_wrelh[(size_t)DM*DM],    g_wrell[(size_t)DM*DM];
__device__ ushort_t g_wouth[(size_t)DM*DM],    g_woutl[(size_t)DM*DM];
__device__ ushort_t g_qrwh[(size_t)BB*LL*DM],  g_qrwl[(size_t)BB*LL*DM];
__device__ ushort_t g_qrrh[(size_t)BB*LL*DM],  g_qrrl[(size_t)BB*LL*DM];
__device__ ushort_t g_kh[(size_t)BB*LL*DM],    g_kl[(size_t)BB*LL*DM];
__device__ ushort_t g_vh[(size_t)BB*LL*DM],    g_vl[(size_t)BB*LL*DM];
__device__ ushort_t g_rkh[(size_t)LL*DM],      g_rkl[(size_t)LL*DM];
__device__ ushort_t g_ctxh[(size_t)BB*LL*DM],  g_ctxl[(size_t)BB*LL*DM];
__device__ int      g_mask_mode;
__device__ unsigned char g_mask[BB*LL];

// ---------------- helpers ----------------
__device__ __forceinline__ uint32_t sptr(const void* p) {
    return (uint32_t)__cvta_generic_to_shared(p);
}
__device__ __forceinline__ void ldsm4(uint32_t (&r)[4], uint32_t addr) {
    asm volatile("ldmatrix.sync.aligned.m8n8.x4.shared.b16 {%0,%1,%2,%3},[%4];"
        : "=r"(r[0]), "=r"(r[1]), "=r"(r[2]), "=r"(r[3]) : "r"(addr));
}
__device__ __forceinline__ void ldsm4t(uint32_t (&r)[4], uint32_t addr) {
    asm volatile("ldmatrix.sync.aligned.m8n8.x4.trans.shared.b16 {%0,%1,%2,%3},[%4];"
        : "=r"(r[0]), "=r"(r[1]), "=r"(r[2]), "=r"(r[3]) : "r"(addr));
}
__device__ __forceinline__ void mma_bf16(float* d, const uint32_t* a, uint32_t b0, uint32_t b1) {
    asm volatile("mma.sync.aligned.m16n8k16.row.col.f32.bf16.bf16.f32 "
        "{%0,%1,%2,%3},{%4,%5,%6,%7},{%8,%9},{%0,%1,%2,%3};"
        : "+f"(d[0]), "+f"(d[1]), "+f"(d[2]), "+f"(d[3])
        : "r"(a[0]), "r"(a[1]), "r"(a[2]), "r"(a[3]), "r"(b0), "r"(b1));
}
__device__ __forceinline__ void split2(float x, float y, uint32_t& h, uint32_t& l) {
    __nv_bfloat162 hv = __floats2bfloat162_rn(x, y);
    float2 hf = __bfloat1622float2(hv);
    __nv_bfloat162 lv = __floats2bfloat162_rn(x - hf.x, y - hf.y);
    h = *reinterpret_cast<uint32_t*>(&hv);
    l = *reinterpret_cast<uint32_t*>(&lv);
}
__device__ __forceinline__ void cpa16(uint32_t dst, const void* src) {
    asm volatile("cp.async.cg.shared.global [%0],[%1],16;" :: "r"(dst), "l"(src));
}
__device__ __forceinline__ void cpa_commit() {
    asm volatile("cp.async.commit_group;");
}

// ---------------- pre-split fp32 -> bf16 hi/lo planes ----------------
__global__ void split_planes(const float* __restrict__ in,
                             ushort_t* __restrict__ oh, ushort_t* __restrict__ ol, int n)
{
    int i = (blockIdx.x * blockDim.x + threadIdx.x) * 2;
    if (i >= n) return;
    uint32_t h, l;
    split2(in[i], in[i + 1], h, l);
    *(uint32_t*)(oh + i) = h;
    *(uint32_t*)(ol + i) = l;
}

// ---------------- mask sniff + normalize ----------------
__global__ void mask_detect(const unsigned char* __restrict__ m) {
    __shared__ int flag_off4, flag_big;
    if (threadIdx.x == 0) { flag_off4 = 0; flag_big = 0; }
    __syncthreads();
    int lo = 0, lb = 0;
    for (int i = threadIdx.x; i < BB * LL; i += blockDim.x) {
        unsigned char v = m[i];
        if (v != 0 && (i & 3) != 0) lo = 1;
        if (v > 1) lb = 1;
    }
    if (lo) atomicOr(&flag_off4, 1);
    if (lb) atomicOr(&flag_big, 1);
    __syncthreads();
    if (threadIdx.x == 0) g_mask_mode = flag_big ? 2 : (flag_off4 ? 0 : 1);
}
__global__ void mask_convert(const void* __restrict__ m) {
    int i = blockIdx.x * blockDim.x + threadIdx.x;
    if (i >= BB * LL) return;
    int mode = g_mask_mode;
    unsigned char r;
    if (mode == 0)      r = ((const unsigned char*)m)[i] != 0;
    else if (mode == 1) r = ((const int*)m)[i] != 0;
    else                r = ((const float*)m)[i] != 0.0f;
    g_mask[i] = r;
}

// superdiagonal of shifted bd: out[p, i, i+1] = 0 (or mask bias)
__global__ void fill_diag() {
    int idx = blockIdx.x * blockDim.x + threadIdx.x;
    int p = idx >> 11, i = idx & 2047;
    if (p >= PAIRS || i >= LL - 1) return;
    int b = p >> 4;
    g_bds[((size_t)p * LL + i) * LL + i + 1] = g_mask[b * LL + i + 1] ? MASKV : 0.f;
}

// ================================================================================
// GEMM NN on pre-split bf16 planes (same as R4: cp.async double-buffered).
// MODE 0: fp32 C. MODE 1: hi/lo plane C. MODE 2: QKV routing epilogue.
// ================================================================================
template <int MODE>
__global__ void __launch_bounds__(256, 2) gemm_v2(
    const ushort_t* __restrict__ Ahg, const ushort_t* __restrict__ Alg,
    const ushort_t* __restrict__ Bhg, const ushort_t* __restrict__ Blg,
    float* __restrict__ C,
    ushort_t* __restrict__ Ch, ushort_t* __restrict__ Cl,
    const float* __restrict__ rwb, const float* __restrict__ rrb,
    int M, int N, int K)
{
    extern __shared__ ushort_t sm[];
    ushort_t* AH = sm;
    ushort_t* AL = AH + 2 * 128 * 40;
    ushort_t* BH = AL + 2 * 128 * 40;
    ushort_t* BL = BH + 2 * 32 * 136;

    const int tid = threadIdx.x, w = tid >> 5, t = tid & 31;
    const int m0 = blockIdx.y * 128, n0 = blockIdx.x * 128;
    const int wm = (w >> 2) * 64, wn = (w & 3) * 32;
    const int g = t >> 2, tg = t & 3;

    float d[4][4][4];
#pragma unroll
    for (int i = 0; i < 4; i++)
#pragma unroll
        for (int j = 0; j < 4; j++)
#pragma unroll
            for (int q = 0; q < 4; q++) d[i][j][q] = 0.f;

    const int nk = K / 32;
    auto issue = [&](int kb, int buf) {
#pragma unroll
        for (int s = 0; s < 2; s++) {
            int idx = tid + 256 * s;
            int row = idx >> 2, seg = (idx & 3) * 8;
            size_t src = (size_t)(m0 + row) * K + kb * 32 + seg;
            uint32_t da = sptr(AH + buf * 5120 + row * 40 + seg);
            cpa16(da, Ahg + src);
            cpa16(da + (uint32_t)((AL - AH) * 2), Alg + src);
        }
#pragma unroll
        for (int s = 0; s < 2; s++) {
            int idx = tid + 256 * s;
            int row = idx >> 4, seg = (idx & 15) * 8;
            size_t src = (size_t)(kb * 32 + row) * N + n0 + seg;
            uint32_t db = sptr(BH + buf * 4352 + row * 136 + seg);
            cpa16(db, Bhg + src);
            cpa16(db + (uint32_t)((BL - BH) * 2), Blg + src);
        }
        cpa_commit();
    };

    issue(0, 0);
    for (int kb = 0; kb < nk; kb++) {
        const int buf = kb & 1;
        if (kb + 1 < nk) {
            issue(kb + 1, buf ^ 1);
            asm volatile("cp.async.wait_group 1;");
        } else {
            asm volatile("cp.async.wait_group 0;");
        }
        __syncthreads();

        const ushort_t* ah_b = AH + buf * 5120;
        const ushort_t* al_b = AL + buf * 5120;
        const ushort_t* bh_b = BH + buf * 4352;
        const ushort_t* bl_b = BL + buf * 4352;
#pragma unroll
        for (int kt = 0; kt < 2; kt++) {
            uint32_t ah[4][4], al[4][4];
#pragma unroll
            for (int mt = 0; mt < 4; mt++) {
                int off = (wm + mt * 16 + (t & 15)) * 40 + kt * 16 + (t >> 4) * 8;
                ldsm4(ah[mt], sptr(ah_b + off));
                ldsm4(al[mt], sptr(al_b + off));
            }
#pragma unroll
            for (int np = 0; np < 2; np++) {
                uint32_t bh[4], bl[4];
                int off = (kt * 16 + (t & 15)) * 136 + wn + np * 16 + (t >> 4) * 8;
                ldsm4t(bh, sptr(bh_b + off));
                ldsm4t(bl, sptr(bl_b + off));
#pragma unroll
                for (int mt = 0; mt < 4; mt++) {
                    mma_bf16(d[mt][2*np],   ah[mt], bh[0], bh[1]);
                    mma_bf16(d[mt][2*np],   al[mt], bh[0], bh[1]);
                    mma_bf16(d[mt][2*np],   ah[mt], bl[0], bl[1]);
                    mma_bf16(d[mt][2*np+1], ah[mt], bh[2], bh[3]);
                    mma_bf16(d[mt][2*np+1], al[mt], bh[2], bh[3]);
                    mma_bf16(d[mt][2*np+1], ah[mt], bl[2], bl[3]);
                }
            }
        }
        __syncthreads();
    }

#pragma unroll
    for (int mt = 0; mt < 4; mt++) {
#pragma unroll
        for (int nt = 0; nt < 4; nt++) {
            int row = m0 + wm + mt * 16 + g;
            int col = n0 + wn + nt * 8 + 2 * tg;
            if (MODE == 0) {
                *(float2*)(C + (size_t)row * N + col)       = make_float2(d[mt][nt][0], d[mt][nt][1]);
                *(float2*)(C + (size_t)(row + 8) * N + col) = make_float2(d[mt][nt][2], d[mt][nt][3]);
            } else if (MODE == 1) {
                uint32_t h, l;
                split2(d[mt][nt][0], d[mt][nt][1], h, l);
                *(uint32_t*)(Ch + (size_t)row * N + col) = h;
                *(uint32_t*)(Cl + (size_t)row * N + col) = l;
                split2(d[mt][nt][2], d[mt][nt][3], h, l);
                *(uint32_t*)(Ch + (size_t)(row + 8) * N + col) = h;
                *(uint32_t*)(Cl + (size_t)(row + 8) * N + col) = l;
            } else {
                int sec = col >> 10;
                int cl  = col & 1023;
                size_t o0 = (size_t)row * DM + cl;
                size_t o1 = (size_t)(row + 8) * DM + cl;
                uint32_t h, l;
                if (sec == 0) {
                    float b0 = rwb[cl], b1 = rwb[cl + 1];
                    float c0 = rrb[cl], c1 = rrb[cl + 1];
                    split2(d[mt][nt][0] + b0, d[mt][nt][1] + b1, h, l);
                    *(uint32_t*)(g_qrwh + o0) = h; *(uint32_t*)(g_qrwl + o0) = l;
                    split2(d[mt][nt][2] + b0, d[mt][nt][3] + b1, h, l);
                    *(uint32_t*)(g_qrwh + o1) = h; *(uint32_t*)(g_qrwl + o1) = l;
                    split2(d[mt][nt][0] + c0, d[mt][nt][1] + c1, h, l);
                    *(uint32_t*)(g_qrrh + o0) = h; *(uint32_t*)(g_qrrl + o0) = l;
                    split2(d[mt][nt][2] + c0, d[mt][nt][3] + c1, h, l);
                    *(uint32_t*)(g_qrrh + o1) = h; *(uint32_t*)(g_qrrl + o1) = l;
                } else if (sec == 1) {
                    split2(d[mt][nt][0], d[mt][nt][1], h, l);
                    *(uint32_t*)(g_kh + o0) = h; *(uint32_t*)(g_kl + o0) = l;
                    split2(d[mt][nt][2], d[mt][nt][3], h, l);
                    *(uint32_t*)(g_kh + o1) = h; *(uint32_t*)(g_kl + o1) = l;
                } else {
                    split2(d[mt][nt][0], d[mt][nt][1], h, l);
                    *(uint32_t*)(g_vh + o0) = h; *(uint32_t*)(g_vl + o0) = l;
                    split2(d[mt][nt][2], d[mt][nt][3], h, l);
                    *(uint32_t*)(g_vh + o1) = h; *(uint32_t*)(g_vl + o1) = l;
                }
            }
        }
    }
}

// ================================================================================
// BD NT GEMM -> SHIFTED store with mask folded.
// bd[ii,r] lands at: (row=ii, j=ii+r-2047) if r>=2047-ii, else (row=ii-1, j=r+ii+1).
// ================================================================================
__device__ __forceinline__ void bds_write(int p, int b, int ii, int r, float v) {
    int row, j;
    if (r >= LL - 1 - ii) { row = ii; j = ii + r - (LL - 1); }
    else { row = ii - 1; j = r + ii + 1; if (row < 0) return; }
    if (g_mask[b * LL + j]) v = MASKV;
    g_bds[((size_t)p * LL + row) * LL + j] = v;
}

__global__ void __launch_bounds__(256) bd_v2()
{
    extern __shared__ ushort_t sm2[];
    ushort_t* Ahs = sm2;
    ushort_t* Als = Ahs + 128 * 72;
    ushort_t* Bhs = Als + 128 * 72;
    ushort_t* Bls = Bhs + 128 * 72;

    const int p = blockIdx.z, b = p >> 4, h = p & 15;
    const int i0 = blockIdx.y * 128, r0 = blockIdx.x * 128;
    const int tid = threadIdx.x, w = tid >> 5, t = tid & 31;
    const int wm = (w >> 2) * 64, wn = (w & 3) * 32;
    const int g = t >> 2, tg = t & 3;

#pragma unroll
    for (int s = 0; s < 4; s++) {
        int idx = tid + 256 * s;
        int row = idx >> 3, dq = (idx & 7) * 8;
        size_t srcA = (size_t)(b * LL + i0 + row) * DM + h * 64 + dq;
        *(uint4*)(&Ahs[row * 72 + dq]) = *(const uint4*)(g_qrrh + srcA);
        *(uint4*)(&Als[row * 72 + dq]) = *(const uint4*)(g_qrrl + srcA);
        size_t srcB = (size_t)(r0 + row) * DM + h * 64 + dq;
        *(uint4*)(&Bhs[row * 72 + dq]) = *(const uint4*)(g_rkh + srcB);
        *(uint4*)(&Bls[row * 72 + dq]) = *(const uint4*)(g_rkl + srcB);
    }
    __syncthreads();

    float d[4][4][4];
#pragma unroll
    for (int i = 0; i < 4; i++)
#pragma unroll
        for (int j = 0; j < 4; j++)
#pragma unroll
            for (int q = 0; q < 4; q++) d[i][j][q] = 0.f;

#pragma unroll
    for (int kt = 0; kt < 4; kt++) {
        uint32_t ah[4][4], al[4][4];
#pragma unroll
        for (int mt = 0; mt < 4; mt++) {
            int off = (wm + mt * 16 + (t & 15)) * 72 + kt * 16 + (t >> 4) * 8;
            ldsm4(ah[mt], sptr(&Ahs[off]));
            ldsm4(al[mt], sptr(&Als[off]));
        }
#pragma unroll
        for (int np = 0; np < 2; np++) {
            uint32_t bh[4], bl[4];
            int nrow = wn + np * 16 + ((t >> 4) << 3) + (t & 7);
            int kcol = kt * 16 + ((t >> 3) & 1) * 8;
            ldsm4(bh, sptr(&Bhs[nrow * 72 + kcol]));
            ldsm4(bl, sptr(&Bls[nrow * 72 + kcol]));
#pragma unroll
            for (int mt = 0; mt < 4; mt++) {
                mma_bf16(d[mt][2*np],   ah[mt], bh[0], bh[1]);
                mma_bf16(d[mt][2*np],   al[mt], bh[0], bh[1]);
                mma_bf16(d[mt][2*np],   ah[mt], bl[0], bl[1]);
                mma_bf16(d[mt][2*np+1], ah[mt], bh[2], bh[3]);
                mma_bf16(d[mt][2*np+1], al[mt], bh[2], bh[3]);
                mma_bf16(d[mt][2*np+1], ah[mt], bl[2], bl[3]);
            }
        }
    }
#pragma unroll
    for (int mt = 0; mt < 4; mt++) {
#pragma unroll
        for (int nt = 0; nt < 4; nt++) {
            int ii0 = i0 + wm + mt * 16 + g;
            int ii1 = ii0 + 8;
            int c0  = r0 + wn + nt * 8 + 2 * tg;
            bds_write(p, b, ii0, c0,     d[mt][nt][0]);
            bds_write(p, b, ii0, c0 + 1, d[mt][nt][1]);
            bds_write(p, b, ii1, c0,     d[mt][nt][2]);
            bds_write(p, b, ii1, c0 + 1, d[mt][nt][3]);
        }
    }
}

// ================================================================================
// Flash attention: coalesced shifted-bd reads, cp.async double-buffered K/V.
// Block = 128 q-rows x (b,h); 8 warps.
// ================================================================================
#define PL (64*72)
__global__ void __launch_bounds__(256) attn_v3()
{
    extern __shared__ ushort_t smA[];
    // buf layout: [buf][plane: Kh,Kl,Vh,Vl][64*72]
    const int it = blockIdx.x, h = blockIdx.y, b = blockIdx.z;
    const int i0 = it * 128;
    const int p = b * NH + h;
    const int tid = threadIdx.x, w = tid >> 5, t = tid & 31;
    const int g = t >> 2, tg = t & 3;

    auto issueKV = [&](int j0, int buf) {
        ushort_t* base = smA + buf * 4 * PL;
#pragma unroll
        for (int s = 0; s < 2; s++) {
            int idx = tid + 256 * s;
            int row = idx >> 3, dq = (idx & 7) * 8;
            size_t src = (size_t)(b * LL + j0 + row) * DM + h * 64 + dq;
            uint32_t dst = sptr(base + row * 72 + dq);
            cpa16(dst,               g_kh + src);
            cpa16(dst + 2 * PL,      g_kl + src);
            cpa16(dst + 4 * PL,      g_vh + src);
            cpa16(dst + 6 * PL,      g_vl + src);
        }
        cpa_commit();
    };

    // prefetch tile 0 into buf0 (overlaps with Q prologue below)
    issueKV(0, 0);

    // Q prologue staged through buf1's K planes
    ushort_t* QSH = smA + 4 * PL;
    ushort_t* QSL = QSH + PL;
    uint32_t qh[4][4], ql[4][4];
#pragma unroll
    for (int half = 0; half < 2; half++) {
#pragma unroll
        for (int s = 0; s < 2; s++) {
            int idx = tid + 256 * s;
            int row = idx >> 3, dq = (idx & 7) * 8;
            size_t src = (size_t)(b * LL + i0 + half * 64 + row) * DM + h * 64 + dq;
            *(uint4*)(&QSH[row * 72 + dq]) = *(const uint4*)(g_qrwh + src);
            *(uint4*)(&QSL[row * 72 + dq]) = *(const uint4*)(g_qrwl + src);
        }
        __syncthreads();
        if ((w >> 2) == half) {
            int mbase = (w & 3) * 16;
#pragma unroll
            for (int kt = 0; kt < 4; kt++) {
                int off = (mbase + (t & 15)) * 72 + kt * 16 + (t >> 4) * 8;
                ldsm4(qh[kt], sptr(&QSH[off]));
                ldsm4(ql[kt], sptr(&QSL[off]));
            }
        }
        __syncthreads();
    }

    float ctx[8][4];
#pragma unroll
    for (int i = 0; i < 8; i++)
#pragma unroll
        for (int q = 0; q < 4; q++) ctx[i][q] = 0.f;
    float m0 = -1e30f, m1 = -1e30f, l0 = 0.f, l1 = 0.f;

    const int ig0 = i0 + w * 16 + g;
    const int ig1 = ig0 + 8;
    const float* bds0 = g_bds + ((size_t)p * LL + ig0) * LL;
    const float* bds1 = g_bds + ((size_t)p * LL + ig1) * LL;

    const int NT = LL / 64;
    for (int jt = 0; jt < NT; jt++) {
        const int j0 = jt * 64;
        const int buf = jt & 1;
        if (jt + 1 < NT) {
            issueKV(j0 + 64, buf ^ 1);
            asm volatile("cp.async.wait_group 1;");
        } else {
            asm volatile("cp.async.wait_group 0;");
        }
        __syncthreads();

        const ushort_t* KSH = smA + buf * 4 * PL;
        const ushort_t* KSL = KSH + PL;
        const ushort_t* VSH = KSH + 2 * PL;
        const ushort_t* VSL = KSH + 3 * PL;

        // S = Qrw . K^T
        float sv[8][4];
#pragma unroll
        for (int i = 0; i < 8; i++)
#pragma unroll
            for (int q = 0; q < 4; q++) sv[i][q] = 0.f;
#pragma unroll
        for (int kt = 0; kt < 4; kt++) {
#pragma unroll
            for (int np = 0; np < 4; np++) {
                uint32_t bh[4], bl[4];
                int nrow = np * 16 + ((t >> 4) << 3) + (t & 7);
                int kcol = kt * 16 + ((t >> 3) & 1) * 8;
                ldsm4(bh, sptr(KSH + nrow * 72 + kcol));
                ldsm4(bl, sptr(KSL + nrow * 72 + kcol));
                mma_bf16(sv[2*np],   qh[kt], bh[0], bh[1]);
                mma_bf16(sv[2*np],   ql[kt], bh[0], bh[1]);
                mma_bf16(sv[2*np],   qh[kt], bl[0], bl[1]);
                mma_bf16(sv[2*np+1], qh[kt], bh[2], bh[3]);
                mma_bf16(sv[2*np+1], ql[kt], bh[2], bh[3]);
                mma_bf16(sv[2*np+1], qh[kt], bl[2], bl[3]);
            }
        }

        // + shifted bd (coalesced), scale (mask already folded)
#pragma unroll
        for (int nt = 0; nt < 8; nt++) {
            int jg = j0 + nt * 8 + 2 * tg;
            float2 b0 = *(const float2*)(bds0 + jg);
            float2 b1 = *(const float2*)(bds1 + jg);
            sv[nt][0] = (sv[nt][0] + b0.x) * SCALE;
            sv[nt][1] = (sv[nt][1] + b0.y) * SCALE;
            sv[nt][2] = (sv[nt][2] + b1.x) * SCALE;
            sv[nt][3] = (sv[nt][3] + b1.y) * SCALE;
        }

        // online softmax
        float r0m = -1e30f, r1m = -1e30f;
#pragma unroll
        for (int nt = 0; nt < 8; nt++) {
            r0m = fmaxf(r0m, fmaxf(sv[nt][0], sv[nt][1]));
            r1m = fmaxf(r1m, fmaxf(sv[nt][2], sv[nt][3]));
        }
        r0m = fmaxf(r0m, __shfl_xor_sync(0xffffffffu, r0m, 1));
        r0m = fmaxf(r0m, __shfl_xor_sync(0xffffffffu, r0m, 2));
        r1m = fmaxf(r1m, __shfl_xor_sync(0xffffffffu, r1m, 1));
        r1m = fmaxf(r1m, __shfl_xor_sync(0xffffffffu, r1m, 2));
        float m0n = fmaxf(m0, r0m), m1n = fmaxf(m1, r1m);
        float f0 = __expf(m0 - m0n), f1 = __expf(m1 - m1n);
        m0 = m0n; m1 = m1n;
        float ps0 = 0.f, ps1 = 0.f;
#pragma unroll
        for (int nt = 0; nt < 8; nt++) {
            sv[nt][0] = __expf(sv[nt][0] - m0n); ps0 += sv[nt][0];
            sv[nt][1] = __expf(sv[nt][1] - m0n); ps0 += sv[nt][1];
            sv[nt][2] = __expf(sv[nt][2] - m1n); ps1 += sv[nt][2];
            sv[nt][3] = __expf(sv[nt][3] - m1n); ps1 += sv[nt][3];
        }
        ps0 += __shfl_xor_sync(0xffffffffu, ps0, 1);
        ps0 += __shfl_xor_sync(0xffffffffu, ps0, 2);
        ps1 += __shfl_xor_sync(0xffffffffu, ps1, 1);
        ps1 += __shfl_xor_sync(0xffffffffu, ps1, 2);
        l0 = l0 * f0 + ps0;
        l1 = l1 * f1 + ps1;
#pragma unroll
        for (int dt = 0; dt < 8; dt++) {
            ctx[dt][0] *= f0; ctx[dt][1] *= f0;
            ctx[dt][2] *= f1; ctx[dt][3] *= f1;
        }

        // ctx += P @ V
#pragma unroll
        for (int kt = 0; kt < 4; kt++) {
            uint32_t ph[4], pl[4];
            split2(sv[2*kt][0],   sv[2*kt][1],   ph[0], pl[0]);
            split2(sv[2*kt][2],   sv[2*kt][3],   ph[1], pl[1]);
            split2(sv[2*kt+1][0], sv[2*kt+1][1], ph[2], pl[2]);
            split2(sv[2*kt+1][2], sv[2*kt+1][3], ph[3], pl[3]);
#pragma unroll
            for (int dp = 0; dp < 4; dp++) {
                uint32_t bh[4], bl[4];
                int off = (kt * 16 + (t & 15)) * 72 + dp * 16 + (t >> 4) * 8;
                ldsm4t(bh, sptr(VSH + off));
                ldsm4t(bl, sptr(VSL + off));
                mma_bf16(ctx[2*dp],   ph, bh[0], bh[1]);
                mma_bf16(ctx[2*dp],   pl, bh[0], bh[1]);
                mma_bf16(ctx[2*dp],   ph, bl[0], bl[1]);
                mma_bf16(ctx[2*dp+1], ph, bh[2], bh[3]);
                mma_bf16(ctx[2*dp+1], pl, bh[2], bh[3]);
                mma_bf16(ctx[2*dp+1], ph, bl[2], bl[3]);
            }
        }
        __syncthreads();
    }

    // epilogue: normalize + emit hi/lo planes for W_out GEMM
    float inv0 = 1.0f / l0, inv1 = 1.0f / l1;
#pragma unroll
    for (int dt = 0; dt < 8; dt++) {
        int col = h * 64 + dt * 8 + 2 * tg;
        size_t o0 = (size_t)(b * LL + ig0) * DM + col;
        size_t o1 = (size_t)(b * LL + ig1) * DM + col;
        uint32_t hh, ll;
        split2(ctx[dt][0] * inv0, ctx[dt][1] * inv0, hh, ll);
        *(uint32_t*)(g_ctxh + o0) = hh; *(uint32_t*)(g_ctxl + o0) = ll;
        split2(ctx[dt][2] * inv1, ctx[dt][3] * inv1, hh, ll);
        *(uint32_t*)(g_ctxh + o1) = hh; *(uint32_t*)(g_ctxl + o1) = ll;
    }
}

// ---------------- residual + LayerNorm ----------------
__global__ void __launch_bounds__(256) ln_kernel(const float* __restrict__ x,
                                                 const float* __restrict__ gamma,
                                                 const float* __restrict__ beta,
                                                 float* __restrict__ out)
{
    const int row = blockIdx.x;
    const int tid = threadIdx.x;
    __shared__ float yb[DM];
    __shared__ float red[2][8];
    __shared__ float stats[2];

    float4 xv = ((const float4*)(x + (size_t)row * DM))[tid];
    float4 av = ((const float4*)(g_att + (size_t)row * DM))[tid];
    float4 y;
    y.x = xv.x + av.x; y.y = xv.y + av.y; y.z = xv.z + av.z; y.w = xv.w + av.w;
    *(float4*)(&yb[tid * 4]) = y;
    float s  = y.x + y.y + y.z + y.w;
    float sq = y.x * y.x + y.y * y.y + y.z * y.z + y.w * y.w;
#pragma unroll
    for (int off = 16; off >= 1; off >>= 1) {
        s  += __shfl_xor_sync(0xffffffffu, s, off);
        sq += __shfl_xor_sync(0xffffffffu, sq, off);
    }
    if ((tid & 31) == 0) { red[0][tid >> 5] = s; red[1][tid >> 5] = sq; }
    __syncthreads();
    if (tid == 0) {
        float ts = 0.f, tq = 0.f;
#pragma unroll
        for (int q = 0; q < 8; q++) { ts += red[0][q]; tq += red[1][q]; }
        float mu = ts * (1.0f / DM);
        float var = tq * (1.0f / DM) - mu * mu;
        stats[0] = mu;
        stats[1] = rsqrtf(var + LN_EPS);
    }
    __syncthreads();
    float mu = stats[0], inv = stats[1];
    float4 gm = ((const float4*)gamma)[tid];
    float4 be = ((const float4*)beta)[tid];
    float4 yy = *(float4*)(&yb[tid * 4]);
    float4 o;
    o.x = (yy.x - mu) * inv * gm.x + be.x;
    o.y = (yy.y - mu) * inv * gm.y + be.y;
    o.z = (yy.z - mu) * inv * gm.z + be.z;
    o.w = (yy.w - mu) * inv * gm.w + be.w;
    ((float4*)(out + (size_t)row * DM))[tid] = o;
}

// ---------------- launch ----------------
extern "C" void kernel_launch(void* const* d_in, const int* in_sizes, int n_in,
                              void* d_out, int out_size)
{
    (void)in_sizes; (void)n_in; (void)out_size;
    const float* x      = (const float*)d_in[0];
    const float* relpos = (const float*)d_in[1];
    const float* rwb    = (const float*)d_in[2];
    const float* rrb    = (const float*)d_in[3];
    const void*  maskp  = d_in[4];
    const float* Wqkv   = (const float*)d_in[5];
    const float* Wrel   = (const float*)d_in[6];
    const float* Wout   = (const float*)d_in[7];
    const float* gamma  = (const float*)d_in[8];
    const float* beta   = (const float*)d_in[9];
    float* out = (float*)d_out;

    ushort_t *xh, *xl, *rph, *rpl, *wqh, *wql, *wrh, *wrl, *woh, *wol;
    ushort_t *rkh, *rkl, *cth, *ctl;
    float* attp;
    cudaGetSymbolAddress((void**)&xh,  g_xh);   cudaGetSymbolAddress((void**)&xl,  g_xl);
    cudaGetSymbolAddress((void**)&rph, g_rph);  cudaGetSymbolAddress((void**)&rpl, g_rpl);
    cudaGetSymbolAddress((void**)&wqh, g_wqkvh);cudaGetSymbolAddress((void**)&wql, g_wqkvl);
    cudaGetSymbolAddress((void**)&wrh, g_wrelh);cudaGetSymbolAddress((void**)&wrl, g_wrell);
    cudaGetSymbolAddress((void**)&woh, g_wouth);cudaGetSymbolAddress((void**)&wol, g_woutl);
    cudaGetSymbolAddress((void**)&rkh, g_rkh);  cudaGetSymbolAddress((void**)&rkl, g_rkl);
    cudaGetSymbolAddress((void**)&cth, g_ctxh); cudaGetSymbolAddress((void**)&ctl, g_ctxl);
    cudaGetSymbolAddress((void**)&attp, g_att);

    const int gemm_smem = (2*128*40 + 2*128*40 + 2*32*136 + 2*32*136) * (int)sizeof(ushort_t);
    cudaFuncSetAttribute(gemm_v2<0>, cudaFuncAttributeMaxDynamicSharedMemorySize, gemm_smem);
    cudaFuncSetAttribute(gemm_v2<1>, cudaFuncAttributeMaxDynamicSharedMemorySize, gemm_smem);
    cudaFuncSetAttribute(gemm_v2<2>, cudaFuncAttributeMaxDynamicSharedMemorySize, gemm_smem);
    const int bd_smem = 4 * 128 * 72 * (int)sizeof(ushort_t);
    cudaFuncSetAttribute(bd_v2, cudaFuncAttributeMaxDynamicSharedMemorySize, bd_smem);
    const int attn_smem = 2 * 4 * PL * (int)sizeof(ushort_t);  // 73728
    cudaFuncSetAttribute(attn_v3, cudaFuncAttributeMaxDynamicSharedMemorySize, attn_smem);

    // launches 1-5: pre-splits (so ncu -s 5 -c 1 captures launch #6 = QKV GEMM)
    split_planes<<<(BB*LL*DM/2 + 255) / 256, 256>>>(x,      xh,  xl,  BB*LL*DM);
    split_planes<<<(LL*DM/2 + 255) / 256, 256>>>(relpos,    rph, rpl, LL*DM);
    split_planes<<<(DM*NQKV/2 + 255) / 256, 256>>>(Wqkv,    wqh, wql, DM*NQKV);
    split_planes<<<(DM*DM/2 + 255) / 256, 256>>>(Wrel,      wrh, wrl, DM*DM);
    split_planes<<<(DM*DM/2 + 255) / 256, 256>>>(Wout,      woh, wol, DM*DM);

    // #6: QKV = x @ W_qkv (routing epilogue)
    gemm_v2<2><<<dim3(NQKV/128, (BB*LL)/128), 256, gemm_smem>>>(
        xh, xl, wqh, wql, nullptr, nullptr, nullptr, rwb, rrb, BB*LL, NQKV, DM);
    // #7: RK planes
    gemm_v2<1><<<dim3(DM/128, LL/128), 256, gemm_smem>>>(
        rph, rpl, wrh, wrl, nullptr, rkh, rkl, nullptr, nullptr, LL, DM, DM);
    // mask normalize (needed by bd + fill_diag)
    mask_detect<<<1, 256>>>((const unsigned char*)maskp);
    mask_convert<<<(BB * LL + 255) / 256, 256>>>(maskp);
    // BD shifted + fold mask
    bd_v2<<<dim3(LL/128, LL/128, PAIRS), 256, bd_smem>>>();
    fill_diag<<<PAIRS * LL / 256, 256>>>();
    // flash attention
    attn_v3<<<dim3(LL/128, NH, BB), 256, attn_smem>>>();
    // attn_out = ctx @ W_out
    gemm_v2<0><<<dim3(DM/128, (BB*LL)/128), 256, gemm_smem>>>(
        cth, ctl, woh, wol, attp, nullptr, nullptr, nullptr, nullptr, BB*LL, DM, DM);
    // residual + layernorm
    ln_kernel<<<BB * LL, 256>>>(x, gamma, beta, out);
}